// round 4
// baseline (speedup 1.0000x reference)
#include <cuda_runtime.h>
#include <math.h>

#define TT   4096
#define BB   16
#define DIN  128
#define DD   256
#define MS   (DD*DD)
#define CH   32
#define NJ   128
#define ALPHA (1.0f - 1.0f/128.0f)
#define BETA  (1.0f/128.0f)

// slots p=0..11 hold M^(2^p)
__device__ __align__(256) float g_MAT[12 * MS];
__device__ __align__(256) float g_QW[MS];
__device__ __align__(256) float g_L[(size_t)TT * BB * DD];   // u -> state, in place, [t][b][d]
__device__ __align__(256) float g_VA[NJ * BB * DD];
__device__ __align__(256) float g_VB[NJ * BB * DD];

// ---------- f32x2 helpers ----------
__device__ __forceinline__ unsigned long long dup2(float x) {
    unsigned long long r; unsigned u = __float_as_uint(x);
    asm("mov.b64 %0, {%1, %1};" : "=l"(r) : "r"(u));
    return r;
}
__device__ __forceinline__ unsigned long long ffma2(unsigned long long a,
                                                    unsigned long long b,
                                                    unsigned long long c) {
    unsigned long long d;
    asm("fma.rn.f32x2 %0, %1, %2, %3;" : "=l"(d) : "l"(a), "l"(b), "l"(c));
    return d;
}
__device__ __forceinline__ float2 f2(unsigned long long v) {
    unsigned lo, hi;
    asm("mov.b64 {%0, %1}, %2;" : "=r"(lo), "=r"(hi) : "l"(v));
    return make_float2(__uint_as_float(lo), __uint_as_float(hi));
}

// ---------- prep: M = alpha*I + beta*A ; QW[n,k] = (2n+1)/16 * parity prefix of W[:,k] ----------
__global__ void __launch_bounds__(256) k_prep(const float* __restrict__ A,
                                              const float* __restrict__ W) {
    int tid = threadIdx.x;
    if (blockIdx.x == 0) {
        float se = 0.f, so = 0.f;   // sums of even/odd rows m < n
        for (int n = 0; n < 256; n++) {
            float c = (float)(2 * n + 1) * 0.0625f;
            g_QW[n * 256 + tid] = c * ((n & 1) ? se : so);
            float w = W[n * 256 + tid];
            if (n & 1) so += w; else se += w;
        }
    } else {
        int i = (blockIdx.x - 1) * 256 + tid;
        float v = BETA * A[i];
        if ((i >> 8) == (i & 255)) v += ALPHA;
        g_MAT[i] = v;
    }
}

// ---------- 64x64-tile fp32 GEMM core ----------
template<int KTOT>
__device__ __forceinline__ void gemm_core(const float* __restrict__ X, int ldx,
                                          const float* __restrict__ Y, int ldy,
                                          int rb, int cb,
                                          unsigned long long (&acc)[4][2]) {
    __shared__ __align__(16) float Ast[16][68];   // [k][row]
    __shared__ __align__(16) float Bs[16][64];
    const int tid  = threadIdx.x;
    const int ty   = tid >> 4, tx = tid & 15;
    const int lrow = tid >> 2, lk4 = (tid & 3) * 4;
    const int lkr  = tid >> 4, lc4 = (tid & 15) * 4;
    for (int kc = 0; kc < KTOT; kc += 16) {
        float4 av = *reinterpret_cast<const float4*>(X + (size_t)(rb + lrow) * ldx + kc + lk4);
        Ast[lk4 + 0][lrow] = av.x; Ast[lk4 + 1][lrow] = av.y;
        Ast[lk4 + 2][lrow] = av.z; Ast[lk4 + 3][lrow] = av.w;
        *reinterpret_cast<float4*>(&Bs[lkr][lc4]) =
            *reinterpret_cast<const float4*>(Y + (size_t)(kc + lkr) * ldy + cb + lc4);
        __syncthreads();
        #pragma unroll
        for (int k = 0; k < 16; k++) {
            float a4[4];
            *reinterpret_cast<float4*>(a4) = *reinterpret_cast<const float4*>(&Ast[k][ty * 4]);
            ulonglong2 bv = *reinterpret_cast<const ulonglong2*>(&Bs[k][tx * 4]);
            #pragma unroll
            for (int i = 0; i < 4; i++) {
                unsigned long long ad = dup2(a4[i]);
                acc[i][0] = ffma2(ad, bv.x, acc[i][0]);
                acc[i][1] = ffma2(ad, bv.y, acc[i][1]);
            }
        }
        __syncthreads();
    }
}

// ---------- repeated squaring: g_MAT[p+1] = g_MAT[p]^2 ----------
__global__ void __launch_bounds__(256) k_sq(int p) {
    const float* X = g_MAT + (size_t)p * MS;
    float*       Z = g_MAT + (size_t)(p + 1) * MS;
    int rb = blockIdx.y * 64, cb = blockIdx.x * 64;
    unsigned long long acc[4][2];
    #pragma unroll
    for (int i = 0; i < 4; i++) { acc[i][0] = 0ull; acc[i][1] = 0ull; }
    gemm_core<256>(X, 256, X, 256, rb, cb, acc);
    int ty = threadIdx.x >> 4, tx = threadIdx.x & 15;
    #pragma unroll
    for (int i = 0; i < 4; i++) {
        float2 v0 = f2(acc[i][0]), v1 = f2(acc[i][1]);
        *reinterpret_cast<float4*>(Z + (size_t)(rb + ty * 4 + i) * 256 + cb + tx * 4) =
            make_float4(v0.x, v0.y, v1.x, v1.y);
    }
}

// ---------- u[t][b][:] = beta * x[b][t][:] @ B ----------
__global__ void __launch_bounds__(256) k_xb(const float* __restrict__ x,
                                            const float* __restrict__ Bm) {
    int rb = blockIdx.y * 64, cb = blockIdx.x * 64;
    unsigned long long acc[4][2];
    #pragma unroll
    for (int i = 0; i < 4; i++) { acc[i][0] = 0ull; acc[i][1] = 0ull; }
    gemm_core<DIN>(x, DIN, Bm, DD, rb, cb, acc);
    int ty = threadIdx.x >> 4, tx = threadIdx.x & 15;
    #pragma unroll
    for (int i = 0; i < 4; i++) {
        int R = rb + ty * 4 + i;
        int b = R >> 12, t = R & 4095;          // x rows are (b, t)
        float2 v0 = f2(acc[i][0]), v1 = f2(acc[i][1]);
        *reinterpret_cast<float4*>(g_L + ((size_t)t * BB + b) * DD + cb + tx * 4) =
            make_float4(BETA * v0.x, BETA * v0.y, BETA * v1.x, BETA * v1.y);
    }
}

// ---------- acc[4rows][4cols] += s[16][256] rows b0.. @ M cols c0.. ----------
__device__ __forceinline__ void mm16(const float (*s)[DD], const float* __restrict__ M,
                                     int b0, int c0, unsigned long long (&acc)[4][2]) {
    ulonglong2 mn[4];
    #pragma unroll
    for (int dd = 0; dd < 4; dd++)
        mn[dd] = *reinterpret_cast<const ulonglong2*>(M + (size_t)dd * DD + c0);
    for (int d4 = 0; d4 < DD; d4 += 4) {
        ulonglong2 mc[4];
        #pragma unroll
        for (int dd = 0; dd < 4; dd++) mc[dd] = mn[dd];
        int dn = (d4 + 4) & (DD - 1);           // prefetch next 4 M rows
        #pragma unroll
        for (int dd = 0; dd < 4; dd++)
            mn[dd] = *reinterpret_cast<const ulonglong2*>(M + (size_t)(dn + dd) * DD + c0);
        float sv[4][4];
        #pragma unroll
        for (int i = 0; i < 4; i++)
            *reinterpret_cast<float4*>(sv[i]) = *reinterpret_cast<const float4*>(&s[b0 + i][d4]);
        #pragma unroll
        for (int dd = 0; dd < 4; dd++)
            #pragma unroll
            for (int i = 0; i < 4; i++) {
                unsigned long long sd = dup2(sv[i][dd]);
                acc[i][0] = ffma2(sd, mc[dd].x, acc[i][0]);
                acc[i][1] = ffma2(sd, mc[dd].y, acc[i][1]);
            }
    }
}

// ---------- per-chunk 32-step recurrence ----------
__device__ __forceinline__ void chunk_run(int j, const float* init, int write_all,
                                          float* tail_out) {
    __shared__ float s[2][BB][DD];
    const int tid = threadIdx.x;
    const int c0 = (tid & 63) * 4;
    const int b0 = (tid >> 6) * 4;
    #pragma unroll
    for (int i = 0; i < 4; i++) {
        float4 v = init ? *reinterpret_cast<const float4*>(init + (size_t)(b0 + i) * DD + c0)
                        : make_float4(0.f, 0.f, 0.f, 0.f);
        *reinterpret_cast<float4*>(&s[0][b0 + i][c0]) = v;
    }
    __syncthreads();
    const float* __restrict__ M = g_MAT;        // M^1
    int cur = 0;
    for (int r = 0; r < CH; r++) {
        float* Lt = g_L + ((size_t)(j * CH + r) * BB) * DD;
        unsigned long long acc[4][2];
        #pragma unroll
        for (int i = 0; i < 4; i++) { acc[i][0] = 0ull; acc[i][1] = 0ull; }
        mm16(s[cur], M, b0, c0, acc);
        #pragma unroll
        for (int i = 0; i < 4; i++) {
            float4 u = *reinterpret_cast<const float4*>(Lt + (size_t)(b0 + i) * DD + c0);
            float2 a0 = f2(acc[i][0]), a1 = f2(acc[i][1]);
            float4 nv = make_float4(u.x + a0.x, u.y + a0.y, u.z + a1.x, u.w + a1.y);
            *reinterpret_cast<float4*>(&s[cur ^ 1][b0 + i][c0]) = nv;
            if (write_all)
                *reinterpret_cast<float4*>(Lt + (size_t)(b0 + i) * DD + c0) = nv;
            if (tail_out && r == CH - 1)
                *reinterpret_cast<float4*>(tail_out + (size_t)(b0 + i) * DD + c0) = nv;
        }
        __syncthreads();
        cur ^= 1;
    }
}

__global__ void __launch_bounds__(256) k_tails() {
    chunk_run(blockIdx.x, (const float*)0, 0, g_VA + (size_t)blockIdx.x * BB * DD);
}

__global__ void __launch_bounds__(256) k_scan() {
    int j = blockIdx.x;
    chunk_run(j, j ? (g_VB + (size_t)(j - 1) * BB * DD) : (const float*)0, 1, (float*)0);
}

// ---------- Hillis level: out_j = in_j + in_{j-2^k} @ M^(32*2^k) ----------
__global__ void __launch_bounds__(256) k_hillis(int level) {
    const float* in  = (level & 1) ? g_VB : g_VA;
    float*       out = (level & 1) ? g_VA : g_VB;
    int j = blockIdx.x;
    int sft = 1 << level;
    const int tid = threadIdx.x;
    const float* inj = in + (size_t)j * BB * DD;
    float*      outj = out + (size_t)j * BB * DD;
    if (j < sft) {
        for (int i = tid; i < BB * DD / 4; i += 256)
            reinterpret_cast<float4*>(outj)[i] = reinterpret_cast<const float4*>(inj)[i];
        return;
    }
    __shared__ float s[BB][DD];
    const float* inp = in + (size_t)(j - sft) * BB * DD;
    for (int i = tid; i < BB * DD / 4; i += 256)
        reinterpret_cast<float4*>(&s[0][0])[i] = reinterpret_cast<const float4*>(inp)[i];
    __syncthreads();
    const int c0 = (tid & 63) * 4;
    const int b0 = (tid >> 6) * 4;
    unsigned long long acc[4][2];
    #pragma unroll
    for (int i = 0; i < 4; i++) { acc[i][0] = 0ull; acc[i][1] = 0ull; }
    mm16(s, g_MAT + (size_t)(5 + level) * MS, b0, c0, acc);
    #pragma unroll
    for (int i = 0; i < 4; i++) {
        float4 u = *reinterpret_cast<const float4*>(inj + (size_t)(b0 + i) * DD + c0);
        float2 a0 = f2(acc[i][0]), a1 = f2(acc[i][1]);
        *reinterpret_cast<float4*>(outj + (size_t)(b0 + i) * DD + c0) =
            make_float4(u.x + a0.x, u.y + a0.y, u.z + a1.x, u.w + a1.y);
    }
}

// ---------- y = tanh(state @ QW + b) ----------
__global__ void __launch_bounds__(256) k_y(const float* __restrict__ bmix,
                                           float* __restrict__ out) {
    int rb = blockIdx.y * 64, cb = blockIdx.x * 64;
    unsigned long long acc[4][2];
    #pragma unroll
    for (int i = 0; i < 4; i++) { acc[i][0] = 0ull; acc[i][1] = 0ull; }
    gemm_core<256>(g_L, DD, g_QW, DD, rb, cb, acc);
    int ty = threadIdx.x >> 4, tx = threadIdx.x & 15;
    int c = cb + tx * 4;
    float4 bv = *reinterpret_cast<const float4*>(bmix + c);
    #pragma unroll
    for (int i = 0; i < 4; i++) {
        int R = rb + ty * 4 + i;
        int t = R >> 4, b = R & 15;             // g_L rows are (t, b)
        float2 a0 = f2(acc[i][0]), a1 = f2(acc[i][1]);
        float4 o = make_float4(tanhf(a0.x + bv.x), tanhf(a0.y + bv.y),
                               tanhf(a1.x + bv.z), tanhf(a1.y + bv.w));
        *reinterpret_cast<float4*>(out + ((size_t)b * TT + t) * DD + c) = o;
    }
}

extern "C" void kernel_launch(void* const* d_in, const int* in_sizes, int n_in,
                              void* d_out, int out_size) {
    const float* x    = (const float*)d_in[0];
    const float* A    = (const float*)d_in[1];
    const float* Bm   = (const float*)d_in[2];
    const float* Wmix = (const float*)d_in[3];
    const float* bmix = (const float*)d_in[4];
    float* out = (float*)d_out;

    k_prep<<<257, 256>>>(A, Wmix);
    for (int p = 0; p < 11; p++)
        k_sq<<<dim3(4, 4), 256>>>(p);
    k_xb<<<dim3(4, 1024), 256>>>(x, Bm);
    k_tails<<<NJ, 256>>>();
    for (int lv = 0; lv < 7; lv++)
        k_hillis<<<NJ, 256>>>(lv);
    k_scan<<<NJ, 256>>>();
    k_y<<<dim3(4, 1024), 256>>>(bmix, out);
}

// round 5
// speedup vs baseline: 1.0485x; 1.0485x over previous
#include <cuda_runtime.h>
#include <math.h>

#define TT   4096
#define BB   16
#define DIN  128
#define DD   256
#define MS   (DD*DD)
#define CH   32
#define NJ   128
#define ALPHA (1.0f - 1.0f/128.0f)
#define BETA  (1.0f/128.0f)

// slots p=0..11 hold M^(2^p)
__device__ __align__(256) float g_MAT[12 * MS];
__device__ __align__(256) float g_QW[MS];
__device__ __align__(256) float g_L[(size_t)TT * BB * DD];   // u, [t][b][d] (never overwritten)
__device__ __align__(256) float g_VA[NJ * BB * DD];
__device__ __align__(256) float g_VB[NJ * BB * DD];

// ---------- f32x2 helpers ----------
__device__ __forceinline__ unsigned long long dup2(float x) {
    unsigned long long r; unsigned u = __float_as_uint(x);
    asm("mov.b64 %0, {%1, %1};" : "=l"(r) : "r"(u));
    return r;
}
__device__ __forceinline__ unsigned long long ffma2(unsigned long long a,
                                                    unsigned long long b,
                                                    unsigned long long c) {
    unsigned long long d;
    asm("fma.rn.f32x2 %0, %1, %2, %3;" : "=l"(d) : "l"(a), "l"(b), "l"(c));
    return d;
}
__device__ __forceinline__ float2 f2(unsigned long long v) {
    unsigned lo, hi;
    asm("mov.b64 {%0, %1}, %2;" : "=r"(lo), "=r"(hi) : "l"(v));
    return make_float2(__uint_as_float(lo), __uint_as_float(hi));
}

// ---------- prep: M = alpha*I + beta*A ; QW[n,k] = (2n+1)/16 * parity prefix of W[:,k] ----------
__global__ void __launch_bounds__(256) k_prep(const float* __restrict__ A,
                                              const float* __restrict__ W) {
    int tid = threadIdx.x;
    if (blockIdx.x == 0) {
        float se = 0.f, so = 0.f;   // sums of even/odd rows m < n
        for (int n = 0; n < 256; n++) {
            float c = (float)(2 * n + 1) * 0.0625f;
            g_QW[n * 256 + tid] = c * ((n & 1) ? se : so);
            float w = W[n * 256 + tid];
            if (n & 1) so += w; else se += w;
        }
    } else {
        int i = (blockIdx.x - 1) * 256 + tid;
        float v = BETA * A[i];
        if ((i >> 8) == (i & 255)) v += ALPHA;
        g_MAT[i] = v;
    }
}

// ---------- repeated squaring, 64 CTAs of 32x32 tiles: g_MAT[p+1] = g_MAT[p]^2 ----------
__global__ void __launch_bounds__(256) k_sq2(int p) {
    const float* __restrict__ X = g_MAT + (size_t)p * MS;
    float*       Z = g_MAT + (size_t)(p + 1) * MS;
    __shared__ __align__(16) float Ast[128][34];  // [k][row], rows of A^T
    __shared__ __align__(16) float Bs[128][32];   // [k][col]
    const int tid = threadIdx.x;
    const int rb = (blockIdx.x >> 3) * 32, cb = (blockIdx.x & 7) * 32;
    const int ty = tid >> 4, tx = tid & 15;       // 16x16 threads, 2x2 outputs
    unsigned long long acc0 = 0ull, acc1 = 0ull;
    const int arow = tid >> 3, ak = (tid & 7) * 4;
    const int bk = tid >> 1,   bc = (tid & 1) * 16;
    for (int kc = 0; kc < 256; kc += 128) {
        #pragma unroll
        for (int ii = 0; ii < 4; ii++) {
            int k = ak + ii * 32;
            float4 av = *reinterpret_cast<const float4*>(X + (size_t)(rb + arow) * DD + kc + k);
            Ast[k + 0][arow] = av.x; Ast[k + 1][arow] = av.y;
            Ast[k + 2][arow] = av.z; Ast[k + 3][arow] = av.w;
            *reinterpret_cast<float4*>(&Bs[bk][bc + ii * 4]) =
                *reinterpret_cast<const float4*>(X + (size_t)(kc + bk) * DD + cb + bc + ii * 4);
        }
        __syncthreads();
        #pragma unroll 8
        for (int k = 0; k < 128; k++) {
            float2 a2 = *reinterpret_cast<const float2*>(&Ast[k][ty * 2]);
            unsigned long long bv = *reinterpret_cast<const unsigned long long*>(&Bs[k][tx * 2]);
            acc0 = ffma2(dup2(a2.x), bv, acc0);
            acc1 = ffma2(dup2(a2.y), bv, acc1);
        }
        __syncthreads();
    }
    float2 v0 = f2(acc0), v1 = f2(acc1);
    *reinterpret_cast<float2*>(Z + (size_t)(rb + ty * 2 + 0) * DD + cb + tx * 2) = v0;
    *reinterpret_cast<float2*>(Z + (size_t)(rb + ty * 2 + 1) * DD + cb + tx * 2) = v1;
}

// ---------- 64x64-tile fp32 GEMM core (for k_xb) ----------
template<int KTOT>
__device__ __forceinline__ void gemm_core(const float* __restrict__ X, int ldx,
                                          const float* __restrict__ Y, int ldy,
                                          int rb, int cb,
                                          unsigned long long (&acc)[4][2]) {
    __shared__ __align__(16) float Ast[16][68];   // [k][row]
    __shared__ __align__(16) float Bs[16][64];
    const int tid  = threadIdx.x;
    const int ty   = tid >> 4, tx = tid & 15;
    const int lrow = tid >> 2, lk4 = (tid & 3) * 4;
    const int lkr  = tid >> 4, lc4 = (tid & 15) * 4;
    for (int kc = 0; kc < KTOT; kc += 16) {
        float4 av = *reinterpret_cast<const float4*>(X + (size_t)(rb + lrow) * ldx + kc + lk4);
        Ast[lk4 + 0][lrow] = av.x; Ast[lk4 + 1][lrow] = av.y;
        Ast[lk4 + 2][lrow] = av.z; Ast[lk4 + 3][lrow] = av.w;
        *reinterpret_cast<float4*>(&Bs[lkr][lc4]) =
            *reinterpret_cast<const float4*>(Y + (size_t)(kc + lkr) * ldy + cb + lc4);
        __syncthreads();
        #pragma unroll
        for (int k = 0; k < 16; k++) {
            float a4[4];
            *reinterpret_cast<float4*>(a4) = *reinterpret_cast<const float4*>(&Ast[k][ty * 4]);
            ulonglong2 bv = *reinterpret_cast<const ulonglong2*>(&Bs[k][tx * 4]);
            #pragma unroll
            for (int i = 0; i < 4; i++) {
                unsigned long long ad = dup2(a4[i]);
                acc[i][0] = ffma2(ad, bv.x, acc[i][0]);
                acc[i][1] = ffma2(ad, bv.y, acc[i][1]);
            }
        }
        __syncthreads();
    }
}

// ---------- u[t][b][:] = beta * x[b][t][:] @ B ----------
__global__ void __launch_bounds__(256) k_xb(const float* __restrict__ x,
                                            const float* __restrict__ Bm) {
    int rb = blockIdx.y * 64, cb = blockIdx.x * 64;
    unsigned long long acc[4][2];
    #pragma unroll
    for (int i = 0; i < 4; i++) { acc[i][0] = 0ull; acc[i][1] = 0ull; }
    gemm_core<DIN>(x, DIN, Bm, DD, rb, cb, acc);
    int ty = threadIdx.x >> 4, tx = threadIdx.x & 15;
    #pragma unroll
    for (int i = 0; i < 4; i++) {
        int R = rb + ty * 4 + i;
        int b = R >> 12, t = R & 4095;          // x rows are (b, t)
        float2 v0 = f2(acc[i][0]), v1 = f2(acc[i][1]);
        *reinterpret_cast<float4*>(g_L + ((size_t)t * BB + b) * DD + cb + tx * 4) =
            make_float4(BETA * v0.x, BETA * v0.y, BETA * v1.x, BETA * v1.y);
    }
}

// ---------- acc[4rows][4cols] += s[16][256] rows b0.. @ M cols c0.. ----------
__device__ __forceinline__ void mm16(const float (*s)[DD], const float* __restrict__ M,
                                     int b0, int c0, unsigned long long (&acc)[4][2]) {
    ulonglong2 mn[4];
    #pragma unroll
    for (int dd = 0; dd < 4; dd++)
        mn[dd] = *reinterpret_cast<const ulonglong2*>(M + (size_t)dd * DD + c0);
    for (int d4 = 0; d4 < DD; d4 += 4) {
        ulonglong2 mc[4];
        #pragma unroll
        for (int dd = 0; dd < 4; dd++) mc[dd] = mn[dd];
        int dn = (d4 + 4) & (DD - 1);           // prefetch next 4 M rows
        #pragma unroll
        for (int dd = 0; dd < 4; dd++)
            mn[dd] = *reinterpret_cast<const ulonglong2*>(M + (size_t)(dn + dd) * DD + c0);
        float sv[4][4];
        #pragma unroll
        for (int i = 0; i < 4; i++)
            *reinterpret_cast<float4*>(sv[i]) = *reinterpret_cast<const float4*>(&s[b0 + i][d4]);
        #pragma unroll
        for (int dd = 0; dd < 4; dd++)
            #pragma unroll
            for (int i = 0; i < 4; i++) {
                unsigned long long sd = dup2(sv[i][dd]);
                acc[i][0] = ffma2(sd, mc[dd].x, acc[i][0]);
                acc[i][1] = ffma2(sd, mc[dd].y, acc[i][1]);
            }
    }
}

// ---------- tails: per-chunk 32-step recurrence from zero, emit tail only ----------
__global__ void __launch_bounds__(256) k_tails() {
    __shared__ float s[2][BB][DD];
    const int tid = threadIdx.x;
    const int c0 = (tid & 63) * 4;
    const int b0 = (tid >> 6) * 4;
    const int j = blockIdx.x;
    #pragma unroll
    for (int i = 0; i < 4; i++)
        *reinterpret_cast<float4*>(&s[0][b0 + i][c0]) = make_float4(0.f, 0.f, 0.f, 0.f);
    __syncthreads();
    int cur = 0;
    for (int r = 0; r < CH; r++) {
        const float* Lt = g_L + ((size_t)(j * CH + r) * BB) * DD;
        unsigned long long acc[4][2];
        #pragma unroll
        for (int i = 0; i < 4; i++) { acc[i][0] = 0ull; acc[i][1] = 0ull; }
        mm16(s[cur], g_MAT, b0, c0, acc);
        #pragma unroll
        for (int i = 0; i < 4; i++) {
            float4 u = *reinterpret_cast<const float4*>(Lt + (size_t)(b0 + i) * DD + c0);
            float2 a0 = f2(acc[i][0]), a1 = f2(acc[i][1]);
            *reinterpret_cast<float4*>(&s[cur ^ 1][b0 + i][c0]) =
                make_float4(u.x + a0.x, u.y + a0.y, u.z + a1.x, u.w + a1.y);
        }
        __syncthreads();
        cur ^= 1;
    }
    float* tail = g_VA + (size_t)j * BB * DD;
    #pragma unroll
    for (int i = 0; i < 4; i++)
        *reinterpret_cast<float4*>(tail + (size_t)(b0 + i) * DD + c0) =
            *reinterpret_cast<const float4*>(&s[cur][b0 + i][c0]);
}

// ---------- Hillis level: out_j = in_j + in_{j-2^k} @ M^(32*2^k) ----------
__global__ void __launch_bounds__(256) k_hillis(int level) {
    const float* in  = (level & 1) ? g_VB : g_VA;
    float*       out = (level & 1) ? g_VA : g_VB;
    int j = blockIdx.x;
    int sft = 1 << level;
    const int tid = threadIdx.x;
    const float* inj = in + (size_t)j * BB * DD;
    float*      outj = out + (size_t)j * BB * DD;
    if (j < sft) {
        for (int i = tid; i < BB * DD / 4; i += 256)
            reinterpret_cast<float4*>(outj)[i] = reinterpret_cast<const float4*>(inj)[i];
        return;
    }
    __shared__ float s[BB][DD];
    const float* inp = in + (size_t)(j - sft) * BB * DD;
    for (int i = tid; i < BB * DD / 4; i += 256)
        reinterpret_cast<float4*>(&s[0][0])[i] = reinterpret_cast<const float4*>(inp)[i];
    __syncthreads();
    const int c0 = (tid & 63) * 4;
    const int b0 = (tid >> 6) * 4;
    unsigned long long acc[4][2];
    #pragma unroll
    for (int i = 0; i < 4; i++) { acc[i][0] = 0ull; acc[i][1] = 0ull; }
    mm16(s, g_MAT + (size_t)(5 + level) * MS, b0, c0, acc);
    #pragma unroll
    for (int i = 0; i < 4; i++) {
        float4 u = *reinterpret_cast<const float4*>(inj + (size_t)(b0 + i) * DD + c0);
        float2 a0 = f2(acc[i][0]), a1 = f2(acc[i][1]);
        *reinterpret_cast<float4*>(outj + (size_t)(b0 + i) * DD + c0) =
            make_float4(u.x + a0.x, u.y + a0.y, u.z + a1.x, u.w + a1.y);
    }
}

// ---------- fused scan + y: recurrence with true init, y = tanh(state@QW + b) ----------
__global__ void __launch_bounds__(256) k_scan_y(const float* __restrict__ bmix,
                                                float* __restrict__ out) {
    __shared__ float s[2][BB][DD];
    const int tid = threadIdx.x;
    const int c0 = (tid & 63) * 4;
    const int b0 = (tid >> 6) * 4;
    const int j = blockIdx.x;
    const float* init = j ? (g_VB + (size_t)(j - 1) * BB * DD) : (const float*)0;
    #pragma unroll
    for (int i = 0; i < 4; i++) {
        float4 v = init ? *reinterpret_cast<const float4*>(init + (size_t)(b0 + i) * DD + c0)
                        : make_float4(0.f, 0.f, 0.f, 0.f);
        *reinterpret_cast<float4*>(&s[0][b0 + i][c0]) = v;
    }
    __syncthreads();
    float4 bv = *reinterpret_cast<const float4*>(bmix + c0);
    int cur = 0;
    for (int r = 0; r < CH; r++) {
        const int t = j * CH + r;
        const float* Lt = g_L + ((size_t)t * BB) * DD;
        unsigned long long acc[4][2];
        #pragma unroll
        for (int i = 0; i < 4; i++) { acc[i][0] = 0ull; acc[i][1] = 0ull; }
        mm16(s[cur], g_MAT, b0, c0, acc);
        #pragma unroll
        for (int i = 0; i < 4; i++) {
            float4 u = *reinterpret_cast<const float4*>(Lt + (size_t)(b0 + i) * DD + c0);
            float2 a0 = f2(acc[i][0]), a1 = f2(acc[i][1]);
            *reinterpret_cast<float4*>(&s[cur ^ 1][b0 + i][c0]) =
                make_float4(u.x + a0.x, u.y + a0.y, u.z + a1.x, u.w + a1.y);
        }
        __syncthreads();
        // y_t = tanh(state_t @ QW + b), state_t = s[cur^1]
        unsigned long long acc2[4][2];
        #pragma unroll
        for (int i = 0; i < 4; i++) { acc2[i][0] = 0ull; acc2[i][1] = 0ull; }
        mm16(s[cur ^ 1], g_QW, b0, c0, acc2);
        #pragma unroll
        for (int i = 0; i < 4; i++) {
            float2 a0 = f2(acc2[i][0]), a1 = f2(acc2[i][1]);
            *reinterpret_cast<float4*>(out + ((size_t)(b0 + i) * TT + t) * DD + c0) =
                make_float4(tanhf(a0.x + bv.x), tanhf(a0.y + bv.y),
                            tanhf(a1.x + bv.z), tanhf(a1.y + bv.w));
        }
        cur ^= 1;
    }
}

extern "C" void kernel_launch(void* const* d_in, const int* in_sizes, int n_in,
                              void* d_out, int out_size) {
    const float* x    = (const float*)d_in[0];
    const float* A    = (const float*)d_in[1];
    const float* Bm   = (const float*)d_in[2];
    const float* Wmix = (const float*)d_in[3];
    const float* bmix = (const float*)d_in[4];
    float* out = (float*)d_out;

    k_prep<<<257, 256>>>(A, Wmix);
    k_xb<<<dim3(4, 1024), 256>>>(x, Bm);
    for (int p = 0; p < 11; p++)
        k_sq2<<<64, 256>>>(p);
    k_tails<<<NJ, 256>>>();
    for (int lv = 0; lv < 7; lv++)
        k_hillis<<<NJ, 256>>>(lv);
    k_scan_y<<<NJ, 256>>>(bmix, out);
}

// round 6
// speedup vs baseline: 1.9645x; 1.8735x over previous
#include <cuda_runtime.h>
#include <math.h>

#define TT   4096
#define BB   16
#define DIN  128
#define DD   256
#define MS   (DD*DD)
#define CH   32
#define NJ   128
#define SSTR 20
#define ALPHA (1.0f - 1.0f/128.0f)
#define BETA  (1.0f/128.0f)

// slots p=0..11 hold M^(2^p)
__device__ __align__(256) float g_MAT[12 * MS];
__device__ __align__(256) float g_QW[MS];
__device__ __align__(256) float g_L[(size_t)TT * BB * DD];   // u -> states (in place), [t][b][d]
__device__ __align__(256) float g_VA[NJ * BB * DD];          // transposed tails [j][d][b]
__device__ __align__(256) float g_VB[NJ * BB * DD];

// ---------- f32x2 helpers ----------
__device__ __forceinline__ unsigned long long dup2(float x) {
    unsigned long long r; unsigned u = __float_as_uint(x);
    asm("mov.b64 %0, {%1, %1};" : "=l"(r) : "r"(u));
    return r;
}
__device__ __forceinline__ unsigned long long ffma2(unsigned long long a,
                                                    unsigned long long b,
                                                    unsigned long long c) {
    unsigned long long d;
    asm("fma.rn.f32x2 %0, %1, %2, %3;" : "=l"(d) : "l"(a), "l"(b), "l"(c));
    return d;
}
__device__ __forceinline__ float2 f2(unsigned long long v) {
    unsigned lo, hi;
    asm("mov.b64 {%0, %1}, %2;" : "=r"(lo), "=r"(hi) : "l"(v));
    return make_float2(__uint_as_float(lo), __uint_as_float(hi));
}
__device__ __forceinline__ float tanha(float x) {
    float y; asm("tanh.approx.f32 %0, %1;" : "=f"(y) : "f"(x)); return y;
}

// ---------- prep ----------
__global__ void __launch_bounds__(256) k_prep(const float* __restrict__ A,
                                              const float* __restrict__ W) {
    int tid = threadIdx.x;
    if (blockIdx.x == 0) {
        float se = 0.f, so = 0.f;
        for (int n = 0; n < 256; n++) {
            float c = (float)(2 * n + 1) * 0.0625f;
            g_QW[n * 256 + tid] = c * ((n & 1) ? se : so);
            float w = W[n * 256 + tid];
            if (n & 1) so += w; else se += w;
        }
    } else {
        int i = (blockIdx.x - 1) * 256 + tid;
        float v = BETA * A[i];
        if ((i >> 8) == (i & 255)) v += ALPHA;
        g_MAT[i] = v;
    }
}

// ---------- squaring tile body (32x32 tiles, 64 CTAs): g_MAT[p+1] = g_MAT[p]^2 ----------
__device__ void sq_body(int p, int bid, float* Ast /*stride 34*/, float* Bs /*stride 32*/) {
    const float* __restrict__ X = g_MAT + (size_t)p * MS;
    float* Z = g_MAT + (size_t)(p + 1) * MS;
    const int tid = threadIdx.x;
    const int rb = (bid >> 3) * 32, cb = (bid & 7) * 32;
    const int ty = tid >> 4, tx = tid & 15;
    unsigned long long acc0 = 0ull, acc1 = 0ull;
    const int arow = tid >> 3, ak = (tid & 7) * 4;
    const int bk = tid >> 1, bc = (tid & 1) * 16;
    for (int kc = 0; kc < 256; kc += 128) {
        #pragma unroll
        for (int ii = 0; ii < 4; ii++) {
            int k = ak + ii * 32;
            float4 av = *reinterpret_cast<const float4*>(X + (size_t)(rb + arow) * DD + kc + k);
            Ast[(k + 0) * 34 + arow] = av.x; Ast[(k + 1) * 34 + arow] = av.y;
            Ast[(k + 2) * 34 + arow] = av.z; Ast[(k + 3) * 34 + arow] = av.w;
            *reinterpret_cast<float4*>(&Bs[bk * 32 + bc + ii * 4]) =
                *reinterpret_cast<const float4*>(X + (size_t)(kc + bk) * DD + cb + bc + ii * 4);
        }
        __syncthreads();
        #pragma unroll 8
        for (int k = 0; k < 128; k++) {
            float2 a2 = *reinterpret_cast<const float2*>(&Ast[k * 34 + ty * 2]);
            unsigned long long bv = *reinterpret_cast<const unsigned long long*>(&Bs[k * 32 + tx * 2]);
            acc0 = ffma2(dup2(a2.x), bv, acc0);
            acc1 = ffma2(dup2(a2.y), bv, acc1);
        }
        __syncthreads();
    }
    float2 v0 = f2(acc0), v1 = f2(acc1);
    *reinterpret_cast<float2*>(Z + (size_t)(rb + ty * 2 + 0) * DD + cb + tx * 2) = v0;
    *reinterpret_cast<float2*>(Z + (size_t)(rb + ty * 2 + 1) * DD + cb + tx * 2) = v1;
}

__global__ void __launch_bounds__(256) k_sq2(int p) {
    __shared__ __align__(16) float sb[8448];
    sq_body(p, blockIdx.x, sb, sb + 4352);
}

// ---------- 64x64 GEMM core (k_xb, k_y) ----------
template<int KTOT>
__device__ __forceinline__ void gemm_core(const float* __restrict__ X, int ldx,
                                          const float* __restrict__ Y, int ldy,
                                          int rb, int cb,
                                          unsigned long long (&acc)[4][2]) {
    __shared__ __align__(16) float Ast[16][68];
    __shared__ __align__(16) float Bs[16][64];
    const int tid  = threadIdx.x;
    const int ty   = tid >> 4, tx = tid & 15;
    const int lrow = tid >> 2, lk4 = (tid & 3) * 4;
    const int lkr  = tid >> 4, lc4 = (tid & 15) * 4;
    for (int kc = 0; kc < KTOT; kc += 16) {
        float4 av = *reinterpret_cast<const float4*>(X + (size_t)(rb + lrow) * ldx + kc + lk4);
        Ast[lk4 + 0][lrow] = av.x; Ast[lk4 + 1][lrow] = av.y;
        Ast[lk4 + 2][lrow] = av.z; Ast[lk4 + 3][lrow] = av.w;
        *reinterpret_cast<float4*>(&Bs[lkr][lc4]) =
            *reinterpret_cast<const float4*>(Y + (size_t)(kc + lkr) * ldy + cb + lc4);
        __syncthreads();
        #pragma unroll
        for (int k = 0; k < 16; k++) {
            float a4[4];
            *reinterpret_cast<float4*>(a4) = *reinterpret_cast<const float4*>(&Ast[k][ty * 4]);
            ulonglong2 bv = *reinterpret_cast<const ulonglong2*>(&Bs[k][tx * 4]);
            #pragma unroll
            for (int i = 0; i < 4; i++) {
                unsigned long long ad = dup2(a4[i]);
                acc[i][0] = ffma2(ad, bv.x, acc[i][0]);
                acc[i][1] = ffma2(ad, bv.y, acc[i][1]);
            }
        }
        __syncthreads();
    }
}

// ---------- u[t][b][:] = beta * x[b][t][:] @ B ----------
__global__ void __launch_bounds__(256) k_xb(const float* __restrict__ x,
                                            const float* __restrict__ Bm) {
    int rb = blockIdx.y * 64, cb = blockIdx.x * 64;
    unsigned long long acc[4][2];
    #pragma unroll
    for (int i = 0; i < 4; i++) { acc[i][0] = 0ull; acc[i][1] = 0ull; }
    gemm_core<DIN>(x, DIN, Bm, DD, rb, cb, acc);
    int ty = threadIdx.x >> 4, tx = threadIdx.x & 15;
    #pragma unroll
    for (int i = 0; i < 4; i++) {
        int R = rb + ty * 4 + i;
        int b = R >> 12, t = R & 4095;
        float2 v0 = f2(acc[i][0]), v1 = f2(acc[i][1]);
        *reinterpret_cast<float4*>(g_L + ((size_t)t * BB + b) * DD + cb + tx * 4) =
            make_float4(BETA * v0.x, BETA * v0.y, BETA * v1.x, BETA * v1.y);
    }
}

// ---------- transposed-state product: acc[c][bp] += sum_{k in half} sT[k][2bp..] * Mx[k][c0+c]
// acc pairs run over b (f32x2 = rows 2bp,2bp+1), c in {0,1}; K-split by thread half ----------
__device__ __forceinline__ void mmT_half(const float* __restrict__ Mx,
                                         const float* sT, int k0, int c0,
                                         unsigned long long (&acc)[2][8]) {
    const float* Mp = Mx + (size_t)k0 * DD + c0;
    unsigned long long mn[8], mc[8];
    #pragma unroll
    for (int i = 0; i < 8; i++)
        mn[i] = *reinterpret_cast<const unsigned long long*>(Mp + (size_t)i * DD);
    for (int kb = 0; kb < 128; kb += 8) {
        #pragma unroll
        for (int i = 0; i < 8; i++) mc[i] = mn[i];
        int nb = (kb + 8) & 127;
        #pragma unroll
        for (int i = 0; i < 8; i++)
            mn[i] = *reinterpret_cast<const unsigned long long*>(Mp + (size_t)(nb + i) * DD);
        #pragma unroll
        for (int kk = 0; kk < 8; kk++) {
            const ulonglong2* sr =
                reinterpret_cast<const ulonglong2*>(sT + (size_t)(k0 + kb + kk) * SSTR);
            ulonglong2 sA = sr[0], sB = sr[1];
            float2 m2 = f2(mc[kk]);
            unsigned long long mx = dup2(m2.x), my = dup2(m2.y);
            acc[0][0] = ffma2(sA.x, mx, acc[0][0]); acc[1][0] = ffma2(sA.x, my, acc[1][0]);
            acc[0][1] = ffma2(sA.y, mx, acc[0][1]); acc[1][1] = ffma2(sA.y, my, acc[1][1]);
            ulonglong2 sC = sr[2], sD = sr[3];
            acc[0][2] = ffma2(sB.x, mx, acc[0][2]); acc[1][2] = ffma2(sB.x, my, acc[1][2]);
            acc[0][3] = ffma2(sB.y, mx, acc[0][3]); acc[1][3] = ffma2(sB.y, my, acc[1][3]);
            acc[0][4] = ffma2(sC.x, mx, acc[0][4]); acc[1][4] = ffma2(sC.x, my, acc[1][4]);
            acc[0][5] = ffma2(sC.y, mx, acc[0][5]); acc[1][5] = ffma2(sC.y, my, acc[1][5]);
            acc[0][6] = ffma2(sD.x, mx, acc[0][6]); acc[1][6] = ffma2(sD.x, my, acc[1][6]);
            acc[0][7] = ffma2(sD.y, mx, acc[0][7]); acc[1][7] = ffma2(sD.y, my, acc[1][7]);
        }
    }
}

// ---------- chunk recurrence (tails / scan) ----------
template<bool WRITE_STATE, bool FROM_INIT>
__device__ void chunk_runT(int j, float* sT, float* red, float* tail_out) {
    const int tid = threadIdx.x;
    const int half = tid >> 7, lt = tid & 127, c0 = lt * 2;
    if (FROM_INIT && j) {
        const float* ip = g_VB + (size_t)(j - 1) * BB * DD;
        for (int f = tid * 4; f < 4096; f += 1024)
            *reinterpret_cast<float4*>(sT + (f >> 4) * SSTR + (f & 15)) =
                *reinterpret_cast<const float4*>(ip + f);
    } else {
        for (int f = tid * 4; f < 4096; f += 1024)
            *reinterpret_cast<float4*>(sT + (f >> 4) * SSTR + (f & 15)) =
                make_float4(0.f, 0.f, 0.f, 0.f);
    }
    __syncthreads();
    for (int r = 0; r < CH; r++) {
        const int t = j * CH + r;
        unsigned long long ureg[16];
        if (half == 0) {
            const float* up = g_L + (size_t)t * BB * DD + c0;
            #pragma unroll
            for (int b = 0; b < 16; b++)
                ureg[b] = *reinterpret_cast<const unsigned long long*>(up + (size_t)b * DD);
        }
        unsigned long long acc[2][8];
        #pragma unroll
        for (int q = 0; q < 8; q++) { acc[0][q] = 0ull; acc[1][q] = 0ull; }
        mmT_half(g_MAT, sT, half * 128, c0, acc);
        __syncthreads();
        if (half == 1) {
            #pragma unroll
            for (int bp = 0; bp < 8; bp++) {
                float2 a0 = f2(acc[0][bp]), a1 = f2(acc[1][bp]);
                red[(2 * bp + 0) * 128 + lt] = a0.x;
                red[(2 * bp + 1) * 128 + lt] = a0.y;
                red[(16 + 2 * bp + 0) * 128 + lt] = a1.x;
                red[(16 + 2 * bp + 1) * 128 + lt] = a1.y;
            }
        }
        __syncthreads();
        if (half == 0) {
            float nx[16], ny[16];
            #pragma unroll
            for (int bp = 0; bp < 8; bp++) {
                float2 a0 = f2(acc[0][bp]), a1 = f2(acc[1][bp]);
                nx[2 * bp] = a0.x; nx[2 * bp + 1] = a0.y;
                ny[2 * bp] = a1.x; ny[2 * bp + 1] = a1.y;
            }
            #pragma unroll
            for (int b = 0; b < 16; b++) {
                float2 u = f2(ureg[b]);
                nx[b] += red[b * 128 + lt] + u.x;
                ny[b] += red[(16 + b) * 128 + lt] + u.y;
            }
            #pragma unroll
            for (int q = 0; q < 4; q++) {
                *reinterpret_cast<float4*>(sT + (size_t)c0 * SSTR + q * 4) =
                    *reinterpret_cast<const float4*>(nx + q * 4);
                *reinterpret_cast<float4*>(sT + (size_t)(c0 + 1) * SSTR + q * 4) =
                    *reinterpret_cast<const float4*>(ny + q * 4);
            }
            if (WRITE_STATE) {
                float* sp = g_L + (size_t)t * BB * DD + c0;
                #pragma unroll
                for (int b = 0; b < 16; b++)
                    *reinterpret_cast<float2*>(sp + (size_t)b * DD) = make_float2(nx[b], ny[b]);
            }
        }
        __syncthreads();
    }
    if (tail_out) {
        for (int f = tid * 4; f < 4096; f += 1024)
            *reinterpret_cast<float4*>(tail_out + f) =
                *reinterpret_cast<const float4*>(sT + (f >> 4) * SSTR + (f & 15));
    }
}

__global__ void __launch_bounds__(256) k_tails() {
    __shared__ __align__(16) float sT[256 * SSTR];
    __shared__ __align__(16) float red[32 * 128];
    chunk_runT<false, false>(blockIdx.x, sT, red, g_VA + (size_t)blockIdx.x * BB * DD);
}

__global__ void __launch_bounds__(256) k_scan() {
    __shared__ __align__(16) float sT[256 * SSTR];
    __shared__ __align__(16) float red[32 * 128];
    chunk_runT<true, true>(blockIdx.x, sT, red, (float*)0);
}

// ---------- Hillis level (transposed domain) + fused next-power squaring ----------
__global__ void __launch_bounds__(256) k_hillis(int level) {
    __shared__ __align__(16) float sbuf[9216];
    int cta = blockIdx.x;
    if (cta >= NJ) {
        if (level < 6) sq_body(5 + level, cta - NJ, sbuf, sbuf + 4352);
        return;
    }
    const float* in  = (level & 1) ? g_VB : g_VA;
    float*       out = (level & 1) ? g_VA : g_VB;
    const int tid = threadIdx.x;
    int j = cta, sft = 1 << level;
    const float* inj = in + (size_t)j * BB * DD;
    float*      outj = out + (size_t)j * BB * DD;
    if (j < sft) {
        for (int f = tid * 4; f < 4096; f += 1024)
            *reinterpret_cast<float4*>(outj + f) = *reinterpret_cast<const float4*>(inj + f);
        return;
    }
    float* sT  = sbuf;
    float* red = sbuf + 256 * SSTR;
    const float* inp = in + (size_t)(j - sft) * BB * DD;
    for (int f = tid * 4; f < 4096; f += 1024)
        *reinterpret_cast<float4*>(sT + (f >> 4) * SSTR + (f & 15)) =
            *reinterpret_cast<const float4*>(inp + f);
    __syncthreads();
    const int half = tid >> 7, lt = tid & 127, c0 = lt * 2;
    unsigned long long acc[2][8];
    #pragma unroll
    for (int q = 0; q < 8; q++) { acc[0][q] = 0ull; acc[1][q] = 0ull; }
    mmT_half(g_MAT + (size_t)(5 + level) * MS, sT, half * 128, c0, acc);
    __syncthreads();
    if (half == 1) {
        #pragma unroll
        for (int bp = 0; bp < 8; bp++) {
            float2 a0 = f2(acc[0][bp]), a1 = f2(acc[1][bp]);
            red[(2 * bp + 0) * 128 + lt] = a0.x;
            red[(2 * bp + 1) * 128 + lt] = a0.y;
            red[(16 + 2 * bp + 0) * 128 + lt] = a1.x;
            red[(16 + 2 * bp + 1) * 128 + lt] = a1.y;
        }
    }
    __syncthreads();
    if (half == 0) {
        float nx[16], ny[16];
        #pragma unroll
        for (int bp = 0; bp < 8; bp++) {
            float2 a0 = f2(acc[0][bp]), a1 = f2(acc[1][bp]);
            nx[2 * bp] = a0.x; nx[2 * bp + 1] = a0.y;
            ny[2 * bp] = a1.x; ny[2 * bp + 1] = a1.y;
        }
        #pragma unroll
        for (int b = 0; b < 16; b++) {
            nx[b] += red[b * 128 + lt];
            ny[b] += red[(16 + b) * 128 + lt];
        }
        #pragma unroll
        for (int q = 0; q < 4; q++) {
            float4 v0 = *reinterpret_cast<const float4*>(inj + (size_t)c0 * 16 + q * 4);
            float4 v1 = *reinterpret_cast<const float4*>(inj + (size_t)(c0 + 1) * 16 + q * 4);
            *reinterpret_cast<float4*>(outj + (size_t)c0 * 16 + q * 4) =
                make_float4(nx[q*4] + v0.x, nx[q*4+1] + v0.y, nx[q*4+2] + v0.z, nx[q*4+3] + v0.w);
            *reinterpret_cast<float4*>(outj + (size_t)(c0 + 1) * 16 + q * 4) =
                make_float4(ny[q*4] + v1.x, ny[q*4+1] + v1.y, ny[q*4+2] + v1.z, ny[q*4+3] + v1.w);
        }
    }
}

// ---------- y = tanh(state @ QW + b) ----------
__global__ void __launch_bounds__(256) k_y(const float* __restrict__ bmix,
                                           float* __restrict__ out) {
    int rb = blockIdx.y * 64, cb = blockIdx.x * 64;
    unsigned long long acc[4][2];
    #pragma unroll
    for (int i = 0; i < 4; i++) { acc[i][0] = 0ull; acc[i][1] = 0ull; }
    gemm_core<256>(g_L, DD, g_QW, DD, rb, cb, acc);
    int ty = threadIdx.x >> 4, tx = threadIdx.x & 15;
    int c = cb + tx * 4;
    float4 bv = *reinterpret_cast<const float4*>(bmix + c);
    #pragma unroll
    for (int i = 0; i < 4; i++) {
        int R = rb + ty * 4 + i;
        int t = R >> 4, b = R & 15;
        float2 a0 = f2(acc[i][0]), a1 = f2(acc[i][1]);
        *reinterpret_cast<float4*>(out + ((size_t)b * TT + t) * DD + c) =
            make_float4(tanha(a0.x + bv.x), tanha(a0.y + bv.y),
                        tanha(a1.x + bv.z), tanha(a1.y + bv.w));
    }
}

extern "C" void kernel_launch(void* const* d_in, const int* in_sizes, int n_in,
                              void* d_out, int out_size) {
    const float* x    = (const float*)d_in[0];
    const float* A    = (const float*)d_in[1];
    const float* Bm   = (const float*)d_in[2];
    const float* Wmix = (const float*)d_in[3];
    const float* bmix = (const float*)d_in[4];
    float* out = (float*)d_out;

    k_prep<<<257, 256>>>(A, Wmix);
    for (int p = 0; p < 5; p++)          // slots 1..5 (M^2 .. M^32)
        k_sq2<<<64, 256>>>(p);
    k_xb<<<dim3(4, 1024), 256>>>(x, Bm);
    k_tails<<<NJ, 256>>>();
    for (int lv = 0; lv < 6; lv++)       // combine + fused squaring for next level
        k_hillis<<<NJ + 64, 256>>>(lv);
    k_hillis<<<NJ, 256>>>(6);
    k_scan<<<NJ, 256>>>();
    k_y<<<dim3(4, 1024), 256>>>(bmix, out);
}

// round 8
// speedup vs baseline: 2.2334x; 1.1369x over previous
#include <cuda_runtime.h>
#include <cuda_bf16.h>
#include <cstdint>
#include <math.h>

#define TT   4096
#define BB   16
#define DIN  128
#define DD   256
#define MS   (DD*DD)
#define CH   32
#define NJ   128
#define SSTR 20
#define ALPHA (1.0f - 1.0f/128.0f)
#define BETA  (1.0f/128.0f)

// slots p=0..11 hold M^(2^p)
__device__ __align__(256) float g_MAT[12 * MS];
__device__ __align__(256) float g_L[(size_t)TT * BB * DD];   // u -> states (in place), [t][b][d]
__device__ __align__(256) float g_VA[NJ * BB * DD];          // transposed tails [j][d][b]
__device__ __align__(256) float g_VB[NJ * BB * DD];
__device__ __align__(256) __nv_bfloat16 g_QWThi[MS];         // QW^T split-hi  [unit][d]
__device__ __align__(256) __nv_bfloat16 g_QWTlo[MS];         // QW^T split-lo

// ---------- f32x2 helpers ----------
__device__ __forceinline__ unsigned long long dup2(float x) {
    unsigned long long r; unsigned u = __float_as_uint(x);
    asm("mov.b64 %0, {%1, %1};" : "=l"(r) : "r"(u));
    return r;
}
__device__ __forceinline__ unsigned long long ffma2(unsigned long long a,
                                                    unsigned long long b,
                                                    unsigned long long c) {
    unsigned long long d;
    asm("fma.rn.f32x2 %0, %1, %2, %3;" : "=l"(d) : "l"(a), "l"(b), "l"(c));
    return d;
}
__device__ __forceinline__ float2 f2(unsigned long long v) {
    unsigned lo, hi;
    asm("mov.b64 {%0, %1}, %2;" : "=r"(lo), "=r"(hi) : "l"(v));
    return make_float2(__uint_as_float(lo), __uint_as_float(hi));
}
__device__ __forceinline__ float tanha(float x) {
    float y; asm("tanh.approx.f32 %0, %1;" : "=f"(y) : "f"(x)); return y;
}
__device__ __forceinline__ uint32_t smem_u32(const void* p) {
    uint32_t a;
    asm("{ .reg .u64 t; cvta.to.shared.u64 t, %1; cvt.u32.u64 %0, t; }" : "=r"(a) : "l"(p));
    return a;
}

// ---------- warp-MMA helpers (baseline PTX, HMMA on sm_103) ----------
#define LDSM_X4(r, a) \
    asm volatile("ldmatrix.sync.aligned.m8n8.x4.shared.b16 {%0,%1,%2,%3}, [%4];" \
        : "=r"((r)[0]), "=r"((r)[1]), "=r"((r)[2]), "=r"((r)[3]) : "r"(a))
#define MMA16816(d, a, b0, b1) \
    asm volatile("mma.sync.aligned.m16n8k16.row.col.f32.bf16.bf16.f32 " \
        "{%0,%1,%2,%3}, {%4,%5,%6,%7}, {%8,%9}, {%0,%1,%2,%3};" \
        : "+f"((d)[0]), "+f"((d)[1]), "+f"((d)[2]), "+f"((d)[3]) \
        : "r"((a)[0]), "r"((a)[1]), "r"((a)[2]), "r"((a)[3]), "r"(b0), "r"(b1))

// ---------- prep: M = alpha*I + beta*A ; QW^T (bf16 hi/lo) via parity prefix sums ----------
__global__ void __launch_bounds__(256) k_prep(const float* __restrict__ A,
                                              const float* __restrict__ W) {
    int tid = threadIdx.x;
    if (blockIdx.x == 0) {
        float se = 0.f, so = 0.f;                 // sums over rows m < n by parity
        for (int n = 0; n < 256; n++) {
            float c = (float)(2 * n + 1) * 0.0625f;
            float qw = c * ((n & 1) ? se : so);   // QW[n][tid]
            __nv_bfloat16 h = __float2bfloat16(qw);
            g_QWThi[tid * 256 + n] = h;
            g_QWTlo[tid * 256 + n] = __float2bfloat16(qw - __bfloat162float(h));
            float w = W[n * 256 + tid];
            if (n & 1) so += w; else se += w;
        }
    } else {
        int i = (blockIdx.x - 1) * 256 + tid;
        float v = BETA * A[i];
        if ((i >> 8) == (i & 255)) v += ALPHA;
        g_MAT[i] = v;
    }
}

// ---------- squaring tile body (32x32 tiles, 64 CTAs): g_MAT[p+1] = g_MAT[p]^2 ----------
__device__ void sq_body(int p, int bid, float* Ast, float* Bs) {
    const float* __restrict__ X = g_MAT + (size_t)p * MS;
    float* Z = g_MAT + (size_t)(p + 1) * MS;
    const int tid = threadIdx.x;
    const int rb = (bid >> 3) * 32, cb = (bid & 7) * 32;
    const int ty = tid >> 4, tx = tid & 15;
    unsigned long long acc0 = 0ull, acc1 = 0ull;
    const int arow = tid >> 3, ak = (tid & 7) * 4;
    const int bk = tid >> 1, bc = (tid & 1) * 16;
    for (int kc = 0; kc < 256; kc += 128) {
        #pragma unroll
        for (int ii = 0; ii < 4; ii++) {
            int k = ak + ii * 32;
            float4 av = *reinterpret_cast<const float4*>(X + (size_t)(rb + arow) * DD + kc + k);
            Ast[(k + 0) * 34 + arow] = av.x; Ast[(k + 1) * 34 + arow] = av.y;
            Ast[(k + 2) * 34 + arow] = av.z; Ast[(k + 3) * 34 + arow] = av.w;
            *reinterpret_cast<float4*>(&Bs[bk * 32 + bc + ii * 4]) =
                *reinterpret_cast<const float4*>(X + (size_t)(kc + bk) * DD + cb + bc + ii * 4);
        }
        __syncthreads();
        #pragma unroll 8
        for (int k = 0; k < 128; k++) {
            float2 a2 = *reinterpret_cast<const float2*>(&Ast[k * 34 + ty * 2]);
            unsigned long long bv = *reinterpret_cast<const unsigned long long*>(&Bs[k * 32 + tx * 2]);
            acc0 = ffma2(dup2(a2.x), bv, acc0);
            acc1 = ffma2(dup2(a2.y), bv, acc1);
        }
        __syncthreads();
    }
    float2 v0 = f2(acc0), v1 = f2(acc1);
    *reinterpret_cast<float2*>(Z + (size_t)(rb + ty * 2 + 0) * DD + cb + tx * 2) = v0;
    *reinterpret_cast<float2*>(Z + (size_t)(rb + ty * 2 + 1) * DD + cb + tx * 2) = v1;
}

__global__ void __launch_bounds__(256) k_sq2(int p) {
    __shared__ __align__(16) float sb[8448];
    sq_body(p, blockIdx.x, sb, sb + 4352);
}

// ---------- 64x64 GEMM core (k_xb) ----------
template<int KTOT>
__device__ __forceinline__ void gemm_core(const float* __restrict__ X, int ldx,
                                          const float* __restrict__ Y, int ldy,
                                          int rb, int cb,
                                          unsigned long long (&acc)[4][2]) {
    __shared__ __align__(16) float Ast[16][68];
    __shared__ __align__(16) float Bs[16][64];
    const int tid  = threadIdx.x;
    const int ty   = tid >> 4, tx = tid & 15;
    const int lrow = tid >> 2, lk4 = (tid & 3) * 4;
    const int lkr  = tid >> 4, lc4 = (tid & 15) * 4;
    for (int kc = 0; kc < KTOT; kc += 16) {
        float4 av = *reinterpret_cast<const float4*>(X + (size_t)(rb + lrow) * ldx + kc + lk4);
        Ast[lk4 + 0][lrow] = av.x; Ast[lk4 + 1][lrow] = av.y;
        Ast[lk4 + 2][lrow] = av.z; Ast[lk4 + 3][lrow] = av.w;
        *reinterpret_cast<float4*>(&Bs[lkr][lc4]) =
            *reinterpret_cast<const float4*>(Y + (size_t)(kc + lkr) * ldy + cb + lc4);
        __syncthreads();
        #pragma unroll
        for (int k = 0; k < 16; k++) {
            float a4[4];
            *reinterpret_cast<float4*>(a4) = *reinterpret_cast<const float4*>(&Ast[k][ty * 4]);
            ulonglong2 bv = *reinterpret_cast<const ulonglong2*>(&Bs[k][tx * 4]);
            #pragma unroll
            for (int i = 0; i < 4; i++) {
                unsigned long long ad = dup2(a4[i]);
                acc[i][0] = ffma2(ad, bv.x, acc[i][0]);
                acc[i][1] = ffma2(ad, bv.y, acc[i][1]);
            }
        }
        __syncthreads();
    }
}

// ---------- u[t][b][:] = beta * x[b][t][:] @ B ----------
__global__ void __launch_bounds__(256) k_xb(const float* __restrict__ x,
                                            const float* __restrict__ Bm) {
    int rb = blockIdx.y * 64, cb = blockIdx.x * 64;
    unsigned long long acc[4][2];
    #pragma unroll
    for (int i = 0; i < 4; i++) { acc[i][0] = 0ull; acc[i][1] = 0ull; }
    gemm_core<DIN>(x, DIN, Bm, DD, rb, cb, acc);
    int ty = threadIdx.x >> 4, tx = threadIdx.x & 15;
    #pragma unroll
    for (int i = 0; i < 4; i++) {
        int R = rb + ty * 4 + i;
        int b = R >> 12, t = R & 4095;
        float2 v0 = f2(acc[i][0]), v1 = f2(acc[i][1]);
        *reinterpret_cast<float4*>(g_L + ((size_t)t * BB + b) * DD + cb + tx * 4) =
            make_float4(BETA * v0.x, BETA * v0.y, BETA * v1.x, BETA * v1.y);
    }
}

// ---------- transposed-state product ----------
__device__ __forceinline__ void mmT_half(const float* __restrict__ Mx,
                                         const float* sT, int k0, int c0,
                                         unsigned long long (&acc)[2][8]) {
    const float* Mp = Mx + (size_t)k0 * DD + c0;
    unsigned long long mn[8], mc[8];
    #pragma unroll
    for (int i = 0; i < 8; i++)
        mn[i] = *reinterpret_cast<const unsigned long long*>(Mp + (size_t)i * DD);
    for (int kb = 0; kb < 128; kb += 8) {
        #pragma unroll
        for (int i = 0; i < 8; i++) mc[i] = mn[i];
        int nb = (kb + 8) & 127;
        #pragma unroll
        for (int i = 0; i < 8; i++)
            mn[i] = *reinterpret_cast<const unsigned long long*>(Mp + (size_t)(nb + i) * DD);
        #pragma unroll
        for (int kk = 0; kk < 8; kk++) {
            const ulonglong2* sr =
                reinterpret_cast<const ulonglong2*>(sT + (size_t)(k0 + kb + kk) * SSTR);
            ulonglong2 sA = sr[0], sB = sr[1];
            float2 m2 = f2(mc[kk]);
            unsigned long long mx = dup2(m2.x), my = dup2(m2.y);
            acc[0][0] = ffma2(sA.x, mx, acc[0][0]); acc[1][0] = ffma2(sA.x, my, acc[1][0]);
            acc[0][1] = ffma2(sA.y, mx, acc[0][1]); acc[1][1] = ffma2(sA.y, my, acc[1][1]);
            ulonglong2 sC = sr[2], sD = sr[3];
            acc[0][2] = ffma2(sB.x, mx, acc[0][2]); acc[1][2] = ffma2(sB.x, my, acc[1][2]);
            acc[0][3] = ffma2(sB.y, mx, acc[0][3]); acc[1][3] = ffma2(sB.y, my, acc[1][3]);
            acc[0][4] = ffma2(sC.x, mx, acc[0][4]); acc[1][4] = ffma2(sC.x, my, acc[1][4]);
            acc[0][5] = ffma2(sC.y, mx, acc[0][5]); acc[1][5] = ffma2(sC.y, my, acc[1][5]);
            acc[0][6] = ffma2(sD.x, mx, acc[0][6]); acc[1][6] = ffma2(sD.x, my, acc[1][6]);
            acc[0][7] = ffma2(sD.y, mx, acc[0][7]); acc[1][7] = ffma2(sD.y, my, acc[1][7]);
        }
    }
}

// ---------- chunk recurrence (tails / scan) ----------
template<bool WRITE_STATE, bool FROM_INIT>
__device__ void chunk_runT(int j, float* sT, float* red, float* tail_out) {
    const int tid = threadIdx.x;
    const int half = tid >> 7, lt = tid & 127, c0 = lt * 2;
    if (FROM_INIT && j) {
        const float* ip = g_VB + (size_t)(j - 1) * BB * DD;
        for (int f = tid * 4; f < 4096; f += 1024)
            *reinterpret_cast<float4*>(sT + (f >> 4) * SSTR + (f & 15)) =
                *reinterpret_cast<const float4*>(ip + f);
    } else {
        for (int f = tid * 4; f < 4096; f += 1024)
            *reinterpret_cast<float4*>(sT + (f >> 4) * SSTR + (f & 15)) =
                make_float4(0.f, 0.f, 0.f, 0.f);
    }
    __syncthreads();
    for (int r = 0; r < CH; r++) {
        const int t = j * CH + r;
        unsigned long long ureg[16];
        if (half == 0) {
            const float* up = g_L + (size_t)t * BB * DD + c0;
            #pragma unroll
            for (int b = 0; b < 16; b++)
                ureg[b] = *reinterpret_cast<const unsigned long long*>(up + (size_t)b * DD);
        }
        unsigned long long acc[2][8];
        #pragma unroll
        for (int q = 0; q < 8; q++) { acc[0][q] = 0ull; acc[1][q] = 0ull; }
        mmT_half(g_MAT, sT, half * 128, c0, acc);
        if (half == 1) {
            #pragma unroll
            for (int bp = 0; bp < 8; bp++) {
                float2 a0 = f2(acc[0][bp]), a1 = f2(acc[1][bp]);
                red[(2 * bp + 0) * 128 + lt] = a0.x;
                red[(2 * bp + 1) * 128 + lt] = a0.y;
                red[(16 + 2 * bp + 0) * 128 + lt] = a1.x;
                red[(16 + 2 * bp + 1) * 128 + lt] = a1.y;
            }
        }
        __syncthreads();
        if (half == 0) {
            float nx[16], ny[16];
            #pragma unroll
            for (int bp = 0; bp < 8; bp++) {
                float2 a0 = f2(acc[0][bp]), a1 = f2(acc[1][bp]);
                nx[2 * bp] = a0.x; nx[2 * bp + 1] = a0.y;
                ny[2 * bp] = a1.x; ny[2 * bp + 1] = a1.y;
            }
            #pragma unroll
            for (int b = 0; b < 16; b++) {
                float2 u = f2(ureg[b]);
                nx[b] += red[b * 128 + lt] + u.x;
                ny[b] += red[(16 + b) * 128 + lt] + u.y;
            }
            #pragma unroll
            for (int q = 0; q < 4; q++) {
                *reinterpret_cast<float4*>(sT + (size_t)c0 * SSTR + q * 4) =
                    *reinterpret_cast<const float4*>(nx + q * 4);
                *reinterpret_cast<float4*>(sT + (size_t)(c0 + 1) * SSTR + q * 4) =
                    *reinterpret_cast<const float4*>(ny + q * 4);
            }
            if (WRITE_STATE) {
                float* sp = g_L + (size_t)t * BB * DD + c0;
                #pragma unroll
                for (int b = 0; b < 16; b++)
                    *reinterpret_cast<float2*>(sp + (size_t)b * DD) = make_float2(nx[b], ny[b]);
            }
        }
        __syncthreads();
    }
    if (tail_out) {
        for (int f = tid * 4; f < 4096; f += 1024)
            *reinterpret_cast<float4*>(tail_out + f) =
                *reinterpret_cast<const float4*>(sT + (f >> 4) * SSTR + (f & 15));
    }
}

__global__ void __launch_bounds__(256) k_tails() {
    __shared__ __align__(16) float sT[256 * SSTR];
    __shared__ __align__(16) float red[32 * 128];
    chunk_runT<false, false>(blockIdx.x, sT, red, g_VA + (size_t)blockIdx.x * BB * DD);
}

__global__ void __launch_bounds__(256) k_scan() {
    __shared__ __align__(16) float sT[256 * SSTR];
    __shared__ __align__(16) float red[32 * 128];
    chunk_runT<true, true>(blockIdx.x, sT, red, (float*)0);
}

// ---------- Hillis level (transposed domain) + fused next-power squaring ----------
__global__ void __launch_bounds__(256) k_hillis(int level) {
    __shared__ __align__(16) float sbuf[9216];
    int cta = blockIdx.x;
    if (cta >= NJ) {
        if (level < 6) sq_body(5 + level, cta - NJ, sbuf, sbuf + 4352);
        return;
    }
    const float* in  = (level & 1) ? g_VB : g_VA;
    float*       out = (level & 1) ? g_VA : g_VB;
    const int tid = threadIdx.x;
    int j = cta, sft = 1 << level;
    const float* inj = in + (size_t)j * BB * DD;
    float*      outj = out + (size_t)j * BB * DD;
    if (j < sft) {
        for (int f = tid * 4; f < 4096; f += 1024)
            *reinterpret_cast<float4*>(outj + f) = *reinterpret_cast<const float4*>(inj + f);
        return;
    }
    float* sT  = sbuf;
    float* red = sbuf + 256 * SSTR;
    const float* inp = in + (size_t)(j - sft) * BB * DD;
    for (int f = tid * 4; f < 4096; f += 1024)
        *reinterpret_cast<float4*>(sT + (f >> 4) * SSTR + (f & 15)) =
            *reinterpret_cast<const float4*>(inp + f);
    __syncthreads();
    const int half = tid >> 7, lt = tid & 127, c0 = lt * 2;
    unsigned long long acc[2][8];
    #pragma unroll
    for (int q = 0; q < 8; q++) { acc[0][q] = 0ull; acc[1][q] = 0ull; }
    mmT_half(g_MAT + (size_t)(5 + level) * MS, sT, half * 128, c0, acc);
    if (half == 1) {
        #pragma unroll
        for (int bp = 0; bp < 8; bp++) {
            float2 a0 = f2(acc[0][bp]), a1 = f2(acc[1][bp]);
            red[(2 * bp + 0) * 128 + lt] = a0.x;
            red[(2 * bp + 1) * 128 + lt] = a0.y;
            red[(16 + 2 * bp + 0) * 128 + lt] = a1.x;
            red[(16 + 2 * bp + 1) * 128 + lt] = a1.y;
        }
    }
    __syncthreads();
    if (half == 0) {
        float nx[16], ny[16];
        #pragma unroll
        for (int bp = 0; bp < 8; bp++) {
            float2 a0 = f2(acc[0][bp]), a1 = f2(acc[1][bp]);
            nx[2 * bp] = a0.x; nx[2 * bp + 1] = a0.y;
            ny[2 * bp] = a1.x; ny[2 * bp + 1] = a1.y;
        }
        #pragma unroll
        for (int b = 0; b < 16; b++) {
            nx[b] += red[b * 128 + lt];
            ny[b] += red[(16 + b) * 128 + lt];
        }
        #pragma unroll
        for (int q = 0; q < 4; q++) {
            float4 v0 = *reinterpret_cast<const float4*>(inj + (size_t)c0 * 16 + q * 4);
            float4 v1 = *reinterpret_cast<const float4*>(inj + (size_t)(c0 + 1) * 16 + q * 4);
            *reinterpret_cast<float4*>(outj + (size_t)c0 * 16 + q * 4) =
                make_float4(nx[q*4] + v0.x, nx[q*4+1] + v0.y, nx[q*4+2] + v0.z, nx[q*4+3] + v0.w);
            *reinterpret_cast<float4*>(outj + (size_t)(c0 + 1) * 16 + q * 4) =
                make_float4(ny[q*4] + v1.x, ny[q*4+1] + v1.y, ny[q*4+2] + v1.z, ny[q*4+3] + v1.w);
        }
    }
}

// ---------- warp-MMA y: y = tanh(state @ QW + b), split-bf16 3-product ----------
// Grid (2, 512): 128x128 D tiles. 8 warps 4x2, 32x64 per warp, K chunks of 64.
__global__ void __launch_bounds__(256) k_y_mma(const float* __restrict__ bmix,
                                               float* __restrict__ out) {
    extern __shared__ __align__(16) char dsm[];
    const int tid = threadIdx.x;
    const int wid = tid >> 5, lane = tid & 31;
    const int rb = blockIdx.y * 128, cb = blockIdx.x * 128;

    uint32_t raw = smem_u32(dsm);
    uint32_t pad = (1024 - (raw & 1023)) & 1023;
    char* base = dsm + pad;
    uint32_t b32 = raw + pad;
    char* smAhi = base;                  // 128 rows x 64 bf16 (128B rows), SW128
    char* smAlo = base + 16384;
    char* smBhi = base + 32768;          // 128 n-rows x 64 k
    char* smBlo = base + 49152;

    const int wm = (wid >> 1) * 32;      // warp row base in tile
    const int wn = (wid & 1) * 64;       // warp col base

    float acc[2][8][4];
    #pragma unroll
    for (int ma = 0; ma < 2; ma++)
        #pragma unroll
        for (int na = 0; na < 8; na++)
            #pragma unroll
            for (int q = 0; q < 4; q++) acc[ma][na][q] = 0.f;

    const int row = tid >> 1;
    const int ch  = (tid & 1) * 32;

    for (int c = 0; c < 4; c++) {
        const int kc = c * 64;
        // A: fp32 states -> hi/lo bf16, swizzled
        #pragma unroll
        for (int q = 0; q < 8; q++) {
            int col = ch + q * 4;
            float4 v = *reinterpret_cast<const float4*>(g_L + (size_t)(rb + row) * DD + kc + col);
            __nv_bfloat16 h0 = __float2bfloat16(v.x), h1 = __float2bfloat16(v.y);
            __nv_bfloat16 h2 = __float2bfloat16(v.z), h3 = __float2bfloat16(v.w);
            __nv_bfloat16 l0 = __float2bfloat16(v.x - __bfloat162float(h0));
            __nv_bfloat16 l1 = __float2bfloat16(v.y - __bfloat162float(h1));
            __nv_bfloat16 l2 = __float2bfloat16(v.z - __bfloat162float(h2));
            __nv_bfloat16 l3 = __float2bfloat16(v.w - __bfloat162float(h3));
            uint32_t boff = row * 128 + col * 2;
            uint32_t sw = boff ^ ((boff >> 3) & 0x70);
            __nv_bfloat162 th0 = __halves2bfloat162(h0, h1), th1 = __halves2bfloat162(h2, h3);
            __nv_bfloat162 tl0 = __halves2bfloat162(l0, l1), tl1 = __halves2bfloat162(l2, l3);
            uint2 uh, ul;
            uh.x = *reinterpret_cast<uint32_t*>(&th0); uh.y = *reinterpret_cast<uint32_t*>(&th1);
            ul.x = *reinterpret_cast<uint32_t*>(&tl0); ul.y = *reinterpret_cast<uint32_t*>(&tl1);
            *reinterpret_cast<uint2*>(smAhi + sw) = uh;
            *reinterpret_cast<uint2*>(smAlo + sw) = ul;
        }
        // B: precomputed bf16 QW^T hi/lo [n][k], swizzled copy
        #pragma unroll
        for (int q = 0; q < 4; q++) {
            int col = ch + q * 8;
            uint32_t boff = row * 128 + col * 2;
            uint32_t sw = boff ^ ((boff >> 3) & 0x70);
            *reinterpret_cast<uint4*>(smBhi + sw) =
                *reinterpret_cast<const uint4*>(g_QWThi + (size_t)(cb + row) * DD + kc + col);
            *reinterpret_cast<uint4*>(smBlo + sw) =
                *reinterpret_cast<const uint4*>(g_QWTlo + (size_t)(cb + row) * DD + kc + col);
        }
        __syncthreads();
        #pragma unroll
        for (int ks = 0; ks < 4; ks++) {
            // A fragments (both matoms, hi+lo)
            uint32_t ah[2][4], al[2][4];
            {
                int r = (lane & 7) + ((lane >> 3) & 1) * 8;
                int kb = ks * 32 + ((lane >> 4) & 1) * 16;
                #pragma unroll
                for (int ma = 0; ma < 2; ma++) {
                    uint32_t off = (wm + ma * 16 + r) * 128 + kb;
                    off ^= (off >> 3) & 0x70;
                    LDSM_X4(ah[ma], b32 + off);
                    LDSM_X4(al[ma], b32 + 16384 + off);
                }
            }
            // B fragments per pair of n-atoms, interleaved with MMA
            {
                int nr = (lane & 7) + ((lane >> 4) & 1) * 8;
                int kb = ks * 32 + ((lane >> 3) & 1) * 16;
                #pragma unroll
                for (int pr = 0; pr < 4; pr++) {
                    uint32_t off = (wn + pr * 16 + nr) * 128 + kb;
                    off ^= (off >> 3) & 0x70;
                    uint32_t bh[4], bl[4];
                    LDSM_X4(bh, b32 + 32768 + off);
                    LDSM_X4(bl, b32 + 49152 + off);
                    #pragma unroll
                    for (int ma = 0; ma < 2; ma++) {
                        MMA16816(acc[ma][pr * 2 + 0], ah[ma], bh[0], bh[1]);
                        MMA16816(acc[ma][pr * 2 + 0], ah[ma], bl[0], bl[1]);
                        MMA16816(acc[ma][pr * 2 + 0], al[ma], bh[0], bh[1]);
                        MMA16816(acc[ma][pr * 2 + 1], ah[ma], bh[2], bh[3]);
                        MMA16816(acc[ma][pr * 2 + 1], ah[ma], bl[2], bl[3]);
                        MMA16816(acc[ma][pr * 2 + 1], al[ma], bh[2], bh[3]);
                    }
                }
            }
        }
        __syncthreads();
    }

    // epilogue: bias + tanh + float2 stores
    const int qr = lane >> 2, qc = (lane & 3) * 2;
    float2 bvv[8];
    #pragma unroll
    for (int na = 0; na < 8; na++)
        bvv[na] = *reinterpret_cast<const float2*>(bmix + cb + wn + na * 8 + qc);
    #pragma unroll
    for (int ma = 0; ma < 2; ma++) {
        int R0 = rb + wm + ma * 16 + qr;
        int t0 = R0 >> 4, bb0 = R0 & 15;
        int R1 = R0 + 8;
        int t1 = R1 >> 4, bb1 = R1 & 15;
        float* o0 = out + ((size_t)bb0 * TT + t0) * DD + cb + wn + qc;
        float* o1 = out + ((size_t)bb1 * TT + t1) * DD + cb + wn + qc;
        #pragma unroll
        for (int na = 0; na < 8; na++) {
            *reinterpret_cast<float2*>(o0 + na * 8) =
                make_float2(tanha(acc[ma][na][0] + bvv[na].x),
                            tanha(acc[ma][na][1] + bvv[na].y));
            *reinterpret_cast<float2*>(o1 + na * 8) =
                make_float2(tanha(acc[ma][na][2] + bvv[na].x),
                            tanha(acc[ma][na][3] + bvv[na].y));
        }
    }
}

extern "C" void kernel_launch(void* const* d_in, const int* in_sizes, int n_in,
                              void* d_out, int out_size) {
    const float* x    = (const float*)d_in[0];
    const float* A    = (const float*)d_in[1];
    const float* Bm   = (const float*)d_in[2];
    const float* Wmix = (const float*)d_in[3];
    const float* bmix = (const float*)d_in[4];
    float* out = (float*)d_out;

    cudaFuncSetAttribute(k_y_mma, cudaFuncAttributeMaxDynamicSharedMemorySize, 66560);

    k_prep<<<257, 256>>>(A, Wmix);
    for (int p = 0; p < 5; p++)          // slots 1..5 (M^2 .. M^32)
        k_sq2<<<64, 256>>>(p);
    k_xb<<<dim3(4, 1024), 256>>>(x, Bm);
    k_tails<<<NJ, 256>>>();
    for (int lv = 0; lv < 6; lv++)       // combine + fused squaring for next level
        k_hillis<<<NJ + 64, 256>>>(lv);
    k_hillis<<<NJ, 256>>>(6);
    k_scan<<<NJ, 256>>>();
    k_y_mma<<<dim3(2, 512), 256, 66560>>>(bmix, out);
}

// round 9
// speedup vs baseline: 3.3027x; 1.4788x over previous
#include <cuda_runtime.h>
#include <cuda_bf16.h>
#include <cstdint>
#include <math.h>

#define TT   4096
#define BB   16
#define DIN  128
#define DD   256
#define MS   (DD*DD)
#define CH   32
#define NJ   128
#define SSTR 20
#define ALPHA (1.0f - 1.0f/128.0f)
#define BETA  (1.0f/128.0f)

// slots p=0..11 hold M^(2^p) (fp32, for Hillis transitions)
__device__ __align__(256) float g_MAT[12 * MS];
__device__ __align__(256) float g_L[(size_t)TT * BB * DD];   // u -> states (in place), [t][b][d]
__device__ __align__(256) float g_VA[NJ * BB * DD];          // transposed tails [j][d][b]
__device__ __align__(256) float g_VB[NJ * BB * DD];
__device__ __align__(256) __nv_bfloat16 g_QWThi[MS];         // QW^T split-hi [unit][d]
__device__ __align__(256) __nv_bfloat16 g_QWTlo[MS];
__device__ __align__(256) __nv_bfloat16 g_MThi[MS];          // M^T split-hi  [n][k]
__device__ __align__(256) __nv_bfloat16 g_MTlo[MS];          // M^T split-lo  [n][k]

// ---------- f32x2 helpers ----------
__device__ __forceinline__ unsigned long long dup2(float x) {
    unsigned long long r; unsigned u = __float_as_uint(x);
    asm("mov.b64 %0, {%1, %1};" : "=l"(r) : "r"(u));
    return r;
}
__device__ __forceinline__ unsigned long long ffma2(unsigned long long a,
                                                    unsigned long long b,
                                                    unsigned long long c) {
    unsigned long long d;
    asm("fma.rn.f32x2 %0, %1, %2, %3;" : "=l"(d) : "l"(a), "l"(b), "l"(c));
    return d;
}
__device__ __forceinline__ float2 f2(unsigned long long v) {
    unsigned lo, hi;
    asm("mov.b64 {%0, %1}, %2;" : "=r"(lo), "=r"(hi) : "l"(v));
    return make_float2(__uint_as_float(lo), __uint_as_float(hi));
}
__device__ __forceinline__ float tanha(float x) {
    float y; asm("tanh.approx.f32 %0, %1;" : "=f"(y) : "f"(x)); return y;
}
__device__ __forceinline__ uint32_t smem_u32(const void* p) {
    uint32_t a;
    asm("{ .reg .u64 t; cvta.to.shared.u64 t, %1; cvt.u32.u64 %0, t; }" : "=r"(a) : "l"(p));
    return a;
}

// ---------- warp-MMA helpers (baseline PTX, HMMA on sm_103) ----------
#define LDSM_X4(r, a) \
    asm volatile("ldmatrix.sync.aligned.m8n8.x4.shared.b16 {%0,%1,%2,%3}, [%4];" \
        : "=r"((r)[0]), "=r"((r)[1]), "=r"((r)[2]), "=r"((r)[3]) : "r"(a))
#define MMA16816(d, a, b0, b1) \
    asm volatile("mma.sync.aligned.m16n8k16.row.col.f32.bf16.bf16.f32 " \
        "{%0,%1,%2,%3}, {%4,%5,%6,%7}, {%8,%9}, {%0,%1,%2,%3};" \
        : "+f"((d)[0]), "+f"((d)[1]), "+f"((d)[2]), "+f"((d)[3]) \
        : "r"((a)[0]), "r"((a)[1]), "r"((a)[2]), "r"((a)[3]), "r"(b0), "r"(b1))

// ---------- prep: M = alpha*I + beta*A (fp32 + bf16-split M^T) ; QW^T hi/lo ----------
__global__ void __launch_bounds__(256) k_prep(const float* __restrict__ A,
                                              const float* __restrict__ W) {
    int tid = threadIdx.x;
    if (blockIdx.x == 0) {
        float se = 0.f, so = 0.f;                 // sums over rows m < n by parity
        for (int n = 0; n < 256; n++) {
            float c = (float)(2 * n + 1) * 0.0625f;
            float qw = c * ((n & 1) ? se : so);   // QW[n][tid]
            __nv_bfloat16 h = __float2bfloat16(qw);
            g_QWThi[tid * 256 + n] = h;
            g_QWTlo[tid * 256 + n] = __float2bfloat16(qw - __bfloat162float(h));
            float w = W[n * 256 + tid];
            if (n & 1) so += w; else se += w;
        }
    } else {
        int i = (blockIdx.x - 1) * 256 + tid;
        int row = i >> 8, col = i & 255;
        float v = BETA * A[i];
        if (row == col) v += ALPHA;
        g_MAT[i] = v;
        __nv_bfloat16 h = __float2bfloat16(v);
        g_MThi[col * 256 + row] = h;                       // MT[n][k] = M[k][n]
        g_MTlo[col * 256 + row] = __float2bfloat16(v - __bfloat162float(h));
    }
}

// ---------- squaring tile body (32x32 tiles, 64 CTAs): g_MAT[p+1] = g_MAT[p]^2 ----------
__device__ void sq_body(int p, int bid, float* Ast, float* Bs) {
    const float* __restrict__ X = g_MAT + (size_t)p * MS;
    float* Z = g_MAT + (size_t)(p + 1) * MS;
    const int tid = threadIdx.x;
    const int rb = (bid >> 3) * 32, cb = (bid & 7) * 32;
    const int ty = tid >> 4, tx = tid & 15;
    unsigned long long acc0 = 0ull, acc1 = 0ull;
    const int arow = tid >> 3, ak = (tid & 7) * 4;
    const int bk = tid >> 1, bc = (tid & 1) * 16;
    for (int kc = 0; kc < 256; kc += 128) {
        #pragma unroll
        for (int ii = 0; ii < 4; ii++) {
            int k = ak + ii * 32;
            float4 av = *reinterpret_cast<const float4*>(X + (size_t)(rb + arow) * DD + kc + k);
            Ast[(k + 0) * 34 + arow] = av.x; Ast[(k + 1) * 34 + arow] = av.y;
            Ast[(k + 2) * 34 + arow] = av.z; Ast[(k + 3) * 34 + arow] = av.w;
            *reinterpret_cast<float4*>(&Bs[bk * 32 + bc + ii * 4]) =
                *reinterpret_cast<const float4*>(X + (size_t)(kc + bk) * DD + cb + bc + ii * 4);
        }
        __syncthreads();
        #pragma unroll 8
        for (int k = 0; k < 128; k++) {
            float2 a2 = *reinterpret_cast<const float2*>(&Ast[k * 34 + ty * 2]);
            unsigned long long bv = *reinterpret_cast<const unsigned long long*>(&Bs[k * 32 + tx * 2]);
            acc0 = ffma2(dup2(a2.x), bv, acc0);
            acc1 = ffma2(dup2(a2.y), bv, acc1);
        }
        __syncthreads();
    }
    float2 v0 = f2(acc0), v1 = f2(acc1);
    *reinterpret_cast<float2*>(Z + (size_t)(rb + ty * 2 + 0) * DD + cb + tx * 2) = v0;
    *reinterpret_cast<float2*>(Z + (size_t)(rb + ty * 2 + 1) * DD + cb + tx * 2) = v1;
}

__global__ void __launch_bounds__(256) k_sq2(int p) {
    __shared__ __align__(16) float sb[8448];
    sq_body(p, blockIdx.x, sb, sb + 4352);
}

// ---------- 64x64 GEMM core (k_xb) ----------
template<int KTOT>
__device__ __forceinline__ void gemm_core(const float* __restrict__ X, int ldx,
                                          const float* __restrict__ Y, int ldy,
                                          int rb, int cb,
                                          unsigned long long (&acc)[4][2]) {
    __shared__ __align__(16) float Ast[16][68];
    __shared__ __align__(16) float Bs[16][64];
    const int tid  = threadIdx.x;
    const int ty   = tid >> 4, tx = tid & 15;
    const int lrow = tid >> 2, lk4 = (tid & 3) * 4;
    const int lkr  = tid >> 4, lc4 = (tid & 15) * 4;
    for (int kc = 0; kc < KTOT; kc += 16) {
        float4 av = *reinterpret_cast<const float4*>(X + (size_t)(rb + lrow) * ldx + kc + lk4);
        Ast[lk4 + 0][lrow] = av.x; Ast[lk4 + 1][lrow] = av.y;
        Ast[lk4 + 2][lrow] = av.z; Ast[lk4 + 3][lrow] = av.w;
        *reinterpret_cast<float4*>(&Bs[lkr][lc4]) =
            *reinterpret_cast<const float4*>(Y + (size_t)(kc + lkr) * ldy + cb + lc4);
        __syncthreads();
        #pragma unroll
        for (int k = 0; k < 16; k++) {
            float a4[4];
            *reinterpret_cast<float4*>(a4) = *reinterpret_cast<const float4*>(&Ast[k][ty * 4]);
            ulonglong2 bv = *reinterpret_cast<const ulonglong2*>(&Bs[k][tx * 4]);
            #pragma unroll
            for (int i = 0; i < 4; i++) {
                unsigned long long ad = dup2(a4[i]);
                acc[i][0] = ffma2(ad, bv.x, acc[i][0]);
                acc[i][1] = ffma2(ad, bv.y, acc[i][1]);
            }
        }
        __syncthreads();
    }
}

// ---------- u[t][b][:] = beta * x[b][t][:] @ B ----------
__global__ void __launch_bounds__(256) k_xb(const float* __restrict__ x,
                                            const float* __restrict__ Bm) {
    int rb = blockIdx.y * 64, cb = blockIdx.x * 64;
    unsigned long long acc[4][2];
    #pragma unroll
    for (int i = 0; i < 4; i++) { acc[i][0] = 0ull; acc[i][1] = 0ull; }
    gemm_core<DIN>(x, DIN, Bm, DD, rb, cb, acc);
    int ty = threadIdx.x >> 4, tx = threadIdx.x & 15;
    #pragma unroll
    for (int i = 0; i < 4; i++) {
        int R = rb + ty * 4 + i;
        int b = R >> 12, t = R & 4095;
        float2 v0 = f2(acc[i][0]), v1 = f2(acc[i][1]);
        *reinterpret_cast<float4*>(g_L + ((size_t)t * BB + b) * DD + cb + tx * 4) =
            make_float4(BETA * v0.x, BETA * v0.y, BETA * v1.x, BETA * v1.y);
    }
}

// ---------- transposed-state product (fp32, used by Hillis) ----------
__device__ __forceinline__ void mmT_half(const float* __restrict__ Mx,
                                         const float* sT, int k0, int c0,
                                         unsigned long long (&acc)[2][8]) {
    const float* Mp = Mx + (size_t)k0 * DD + c0;
    unsigned long long mn[8], mc[8];
    #pragma unroll
    for (int i = 0; i < 8; i++)
        mn[i] = *reinterpret_cast<const unsigned long long*>(Mp + (size_t)i * DD);
    for (int kb = 0; kb < 128; kb += 8) {
        #pragma unroll
        for (int i = 0; i < 8; i++) mc[i] = mn[i];
        int nb = (kb + 8) & 127;
        #pragma unroll
        for (int i = 0; i < 8; i++)
            mn[i] = *reinterpret_cast<const unsigned long long*>(Mp + (size_t)(nb + i) * DD);
        #pragma unroll
        for (int kk = 0; kk < 8; kk++) {
            const ulonglong2* sr =
                reinterpret_cast<const ulonglong2*>(sT + (size_t)(k0 + kb + kk) * SSTR);
            ulonglong2 sA = sr[0], sB = sr[1];
            float2 m2 = f2(mc[kk]);
            unsigned long long mx = dup2(m2.x), my = dup2(m2.y);
            acc[0][0] = ffma2(sA.x, mx, acc[0][0]); acc[1][0] = ffma2(sA.x, my, acc[1][0]);
            acc[0][1] = ffma2(sA.y, mx, acc[0][1]); acc[1][1] = ffma2(sA.y, my, acc[1][1]);
            ulonglong2 sC = sr[2], sD = sr[3];
            acc[0][2] = ffma2(sB.x, mx, acc[0][2]); acc[1][2] = ffma2(sB.x, my, acc[1][2]);
            acc[0][3] = ffma2(sB.y, mx, acc[0][3]); acc[1][3] = ffma2(sB.y, my, acc[1][3]);
            acc[0][4] = ffma2(sC.x, mx, acc[0][4]); acc[1][4] = ffma2(sC.x, my, acc[1][4]);
            acc[0][5] = ffma2(sC.y, mx, acc[0][5]); acc[1][5] = ffma2(sC.y, my, acc[1][5]);
            acc[0][6] = ffma2(sD.x, mx, acc[0][6]); acc[1][6] = ffma2(sD.x, my, acc[1][6]);
            acc[0][7] = ffma2(sD.y, mx, acc[0][7]); acc[1][7] = ffma2(sD.y, my, acc[1][7]);
        }
    }
}

// ---------- HMMA chunk recurrence: state = state@M + u, 32 steps ----------
// 8 warps, warp w owns n-slice [w*32, w*32+32). M^T_hi in registers (B frags),
// M^T_lo in smem (ldmatrix). State double-buffered in smem as bf16 hi/lo,
// 528B row stride (conflict-free ldmatrix). acc (fp32 C frag) initialized from u.
#define MTLO_OFF 0
#define SH_OFF   135168
#define SL_OFF   152064
#define CHSMEM   168960
template<bool WRITE_STATE, bool FROM_INIT>
__device__ void chunk_mma(int j) {
    extern __shared__ __align__(16) char cs[];
    __nv_bfloat16* MTlo = reinterpret_cast<__nv_bfloat16*>(cs + MTLO_OFF);   // [256][264]
    const int tid = threadIdx.x, lane = tid & 31, wid = tid >> 5;
    const int wn = wid * 32;
    const int qr = lane >> 2, qc = (lane & 3) * 2;

    // copy M^T_lo into padded smem (row tid, 256 bf16 = 32 uint4)
    {
        const uint4* s = reinterpret_cast<const uint4*>(g_MTlo + (size_t)tid * 256);
        uint4* d = reinterpret_cast<uint4*>(MTlo + (size_t)tid * 264);
        #pragma unroll
        for (int i = 0; i < 32; i++) d[i] = s[i];
    }
    // preload M^T_hi B-fragments into registers
    uint32_t Bhi[16][4][2];
    {
        const int bn = lane >> 2, bk = (lane & 3) * 2;
        #pragma unroll
        for (int q = 0; q < 16; q++)
            #pragma unroll
            for (int na = 0; na < 4; na++) {
                const __nv_bfloat16* p = g_MThi + (size_t)(wn + na * 8 + bn) * 256 + q * 16 + bk;
                Bhi[q][na][0] = *reinterpret_cast<const uint32_t*>(p);
                Bhi[q][na][1] = *reinterpret_cast<const uint32_t*>(p + 8);
            }
    }
    // init state buffers (buf 0)
    if (FROM_INIT && j) {
        const float* ip = g_VB + (size_t)(j - 1) * 4096;      // [d][b]
        for (int f = tid; f < 4096; f += 256) {
            int d = f >> 4, b = f & 15;
            float v = ip[f];
            __nv_bfloat16 h = __float2bfloat16(v);
            *reinterpret_cast<__nv_bfloat16*>(cs + SH_OFF + b * 528 + d * 2) = h;
            *reinterpret_cast<__nv_bfloat16*>(cs + SL_OFF + b * 528 + d * 2) =
                __float2bfloat16(v - __bfloat162float(h));
        }
    } else {
        for (int f = tid; f < 4096; f += 256) {
            int d = f >> 4, b = f & 15;
            *reinterpret_cast<unsigned short*>(cs + SH_OFF + b * 528 + d * 2) = 0;
            *reinterpret_cast<unsigned short*>(cs + SL_OFF + b * 528 + d * 2) = 0;
        }
    }
    __syncthreads();

    // ldmatrix lane offsets
    const uint32_t base32 = smem_u32(cs);
    const int arow = (lane & 7) + ((lane >> 3) & 1) * 8;
    const uint32_t aoff = arow * 528 + ((lane >> 4) & 1) * 16;
    const int nr = (lane & 7) + ((lane >> 4) & 1) * 8;
    const uint32_t boff0 = base32 + MTLO_OFF + (wn +  0 + nr) * 528 + ((lane >> 3) & 1) * 16;
    const uint32_t boff1 = base32 + MTLO_OFF + (wn + 16 + nr) * 528 + ((lane >> 3) & 1) * 16;

    // u prefetch for step 0
    float2 u0[4], u1[4];
    {
        const float* up = g_L + (size_t)(j * CH) * 4096;
        #pragma unroll
        for (int na = 0; na < 4; na++) {
            int col = wn + na * 8 + qc;
            u0[na] = *reinterpret_cast<const float2*>(up + (size_t)qr * 256 + col);
            u1[na] = *reinterpret_cast<const float2*>(up + (size_t)(qr + 8) * 256 + col);
        }
    }

    int cur = 0;
    for (int r = 0; r < CH; r++) {
        const int t = j * CH + r;
        float acc[4][4];
        #pragma unroll
        for (int na = 0; na < 4; na++) {
            acc[na][0] = u0[na].x; acc[na][1] = u0[na].y;
            acc[na][2] = u1[na].x; acc[na][3] = u1[na].y;
        }
        if (r + 1 < CH) {
            const float* up = g_L + (size_t)(t + 1) * 4096;
            #pragma unroll
            for (int na = 0; na < 4; na++) {
                int col = wn + na * 8 + qc;
                u0[na] = *reinterpret_cast<const float2*>(up + (size_t)qr * 256 + col);
                u1[na] = *reinterpret_cast<const float2*>(up + (size_t)(qr + 8) * 256 + col);
            }
        }
        const uint32_t shb = base32 + (cur ? SH_OFF + 8448 : SH_OFF) + aoff;
        const uint32_t slb = base32 + (cur ? SL_OFF + 8448 : SL_OFF) + aoff;
        #pragma unroll
        for (int q = 0; q < 16; q++) {
            uint32_t ah[4], al[4], bl0[4], bl1[4];
            LDSM_X4(ah, shb + q * 32);
            LDSM_X4(al, slb + q * 32);
            LDSM_X4(bl0, boff0 + q * 32);
            LDSM_X4(bl1, boff1 + q * 32);
            MMA16816(acc[0], ah, Bhi[q][0][0], Bhi[q][0][1]);
            MMA16816(acc[0], al, Bhi[q][0][0], Bhi[q][0][1]);
            MMA16816(acc[0], ah, bl0[0], bl0[1]);
            MMA16816(acc[1], ah, Bhi[q][1][0], Bhi[q][1][1]);
            MMA16816(acc[1], al, Bhi[q][1][0], Bhi[q][1][1]);
            MMA16816(acc[1], ah, bl0[2], bl0[3]);
            MMA16816(acc[2], ah, Bhi[q][2][0], Bhi[q][2][1]);
            MMA16816(acc[2], al, Bhi[q][2][0], Bhi[q][2][1]);
            MMA16816(acc[2], ah, bl1[0], bl1[1]);
            MMA16816(acc[3], ah, Bhi[q][3][0], Bhi[q][3][1]);
            MMA16816(acc[3], al, Bhi[q][3][0], Bhi[q][3][1]);
            MMA16816(acc[3], ah, bl1[2], bl1[3]);
        }
        if (!WRITE_STATE && r == CH - 1) {
            // final tail -> g_VA[j] transposed [d][b]
            float* tp = g_VA + (size_t)j * 4096;
            #pragma unroll
            for (int na = 0; na < 4; na++) {
                int col = wn + na * 8 + qc;
                tp[(col + 0) * 16 + qr]     = acc[na][0];
                tp[(col + 1) * 16 + qr]     = acc[na][1];
                tp[(col + 0) * 16 + qr + 8] = acc[na][2];
                tp[(col + 1) * 16 + qr + 8] = acc[na][3];
            }
        } else {
            const int nxt = cur ^ 1;
            char* shn = cs + (nxt ? SH_OFF + 8448 : SH_OFF);
            char* sln = cs + (nxt ? SL_OFF + 8448 : SL_OFF);
            #pragma unroll
            for (int na = 0; na < 4; na++) {
                int col = wn + na * 8 + qc;
                {
                    float v0 = acc[na][0], v1 = acc[na][1];
                    __nv_bfloat16 h0 = __float2bfloat16(v0), h1 = __float2bfloat16(v1);
                    __nv_bfloat162 hh = __halves2bfloat162(h0, h1);
                    __nv_bfloat162 ll = __halves2bfloat162(
                        __float2bfloat16(v0 - __bfloat162float(h0)),
                        __float2bfloat16(v1 - __bfloat162float(h1)));
                    *reinterpret_cast<uint32_t*>(shn + qr * 528 + col * 2) =
                        *reinterpret_cast<uint32_t*>(&hh);
                    *reinterpret_cast<uint32_t*>(sln + qr * 528 + col * 2) =
                        *reinterpret_cast<uint32_t*>(&ll);
                }
                {
                    float v0 = acc[na][2], v1 = acc[na][3];
                    __nv_bfloat16 h0 = __float2bfloat16(v0), h1 = __float2bfloat16(v1);
                    __nv_bfloat162 hh = __halves2bfloat162(h0, h1);
                    __nv_bfloat162 ll = __halves2bfloat162(
                        __float2bfloat16(v0 - __bfloat162float(h0)),
                        __float2bfloat16(v1 - __bfloat162float(h1)));
                    *reinterpret_cast<uint32_t*>(shn + (qr + 8) * 528 + col * 2) =
                        *reinterpret_cast<uint32_t*>(&hh);
                    *reinterpret_cast<uint32_t*>(sln + (qr + 8) * 528 + col * 2) =
                        *reinterpret_cast<uint32_t*>(&ll);
                }
                if (WRITE_STATE) {
                    float* sp = g_L + (size_t)t * 4096;
                    *reinterpret_cast<float2*>(sp + (size_t)qr * 256 + col) =
                        make_float2(acc[na][0], acc[na][1]);
                    *reinterpret_cast<float2*>(sp + (size_t)(qr + 8) * 256 + col) =
                        make_float2(acc[na][2], acc[na][3]);
                }
            }
            __syncthreads();
            cur = nxt;
        }
    }
}

__global__ void __launch_bounds__(256) k_tails2() { chunk_mma<false, false>(blockIdx.x); }
__global__ void __launch_bounds__(256) k_scan2()  { chunk_mma<true,  true >(blockIdx.x); }

// ---------- Hillis level (transposed domain) + fused next-power squaring ----------
__global__ void __launch_bounds__(256) k_hillis(int level) {
    __shared__ __align__(16) float sbuf[9216];
    int cta = blockIdx.x;
    if (cta >= NJ) {
        if (level < 6) sq_body(5 + level, cta - NJ, sbuf, sbuf + 4352);
        return;
    }
    const float* in  = (level & 1) ? g_VB : g_VA;
    float*       out = (level & 1) ? g_VA : g_VB;
    const int tid = threadIdx.x;
    int j = cta, sft = 1 << level;
    const float* inj = in + (size_t)j * BB * DD;
    float*      outj = out + (size_t)j * BB * DD;
    if (j < sft) {
        for (int f = tid * 4; f < 4096; f += 1024)
            *reinterpret_cast<float4*>(outj + f) = *reinterpret_cast<const float4*>(inj + f);
        return;
    }
    float* sT  = sbuf;
    float* red = sbuf + 256 * SSTR;
    const float* inp = in + (size_t)(j - sft) * BB * DD;
    for (int f = tid * 4; f < 4096; f += 1024)
        *reinterpret_cast<float4*>(sT + (f >> 4) * SSTR + (f & 15)) =
            *reinterpret_cast<const float4*>(inp + f);
    __syncthreads();
    const int half = tid >> 7, lt = tid & 127, c0 = lt * 2;
    unsigned long long acc[2][8];
    #pragma unroll
    for (int q = 0; q < 8; q++) { acc[0][q] = 0ull; acc[1][q] = 0ull; }
    mmT_half(g_MAT + (size_t)(5 + level) * MS, sT, half * 128, c0, acc);
    if (half == 1) {
        #pragma unroll
        for (int bp = 0; bp < 8; bp++) {
            float2 a0 = f2(acc[0][bp]), a1 = f2(acc[1][bp]);
            red[(2 * bp + 0) * 128 + lt] = a0.x;
            red[(2 * bp + 1) * 128 + lt] = a0.y;
            red[(16 + 2 * bp + 0) * 128 + lt] = a1.x;
            red[(16 + 2 * bp + 1) * 128 + lt] = a1.y;
        }
    }
    __syncthreads();
    if (half == 0) {
        float nx[16], ny[16];
        #pragma unroll
        for (int bp = 0; bp < 8; bp++) {
            float2 a0 = f2(acc[0][bp]), a1 = f2(acc[1][bp]);
            nx[2 * bp] = a0.x; nx[2 * bp + 1] = a0.y;
            ny[2 * bp] = a1.x; ny[2 * bp + 1] = a1.y;
        }
        #pragma unroll
        for (int b = 0; b < 16; b++) {
            nx[b] += red[b * 128 + lt];
            ny[b] += red[(16 + b) * 128 + lt];
        }
        #pragma unroll
        for (int q = 0; q < 4; q++) {
            float4 v0 = *reinterpret_cast<const float4*>(inj + (size_t)c0 * 16 + q * 4);
            float4 v1 = *reinterpret_cast<const float4*>(inj + (size_t)(c0 + 1) * 16 + q * 4);
            *reinterpret_cast<float4*>(outj + (size_t)c0 * 16 + q * 4) =
                make_float4(nx[q*4] + v0.x, nx[q*4+1] + v0.y, nx[q*4+2] + v0.z, nx[q*4+3] + v0.w);
            *reinterpret_cast<float4*>(outj + (size_t)(c0 + 1) * 16 + q * 4) =
                make_float4(ny[q*4] + v1.x, ny[q*4+1] + v1.y, ny[q*4+2] + v1.z, ny[q*4+3] + v1.w);
        }
    }
}

// ---------- warp-MMA y: y = tanh(state @ QW + b), split-bf16 3-product ----------
__global__ void __launch_bounds__(256) k_y_mma(const float* __restrict__ bmix,
                                               float* __restrict__ out) {
    extern __shared__ __align__(16) char dsm[];
    const int tid = threadIdx.x;
    const int wid = tid >> 5, lane = tid & 31;
    const int rb = blockIdx.y * 128, cb = blockIdx.x * 128;

    uint32_t raw = smem_u32(dsm);
    uint32_t pad = (1024 - (raw & 1023)) & 1023;
    char* base = dsm + pad;
    uint32_t b32 = raw + pad;
    char* smAhi = base;
    char* smAlo = base + 16384;
    char* smBhi = base + 32768;
    char* smBlo = base + 49152;

    const int wm = (wid >> 1) * 32;
    const int wn = (wid & 1) * 64;

    float acc[2][8][4];
    #pragma unroll
    for (int ma = 0; ma < 2; ma++)
        #pragma unroll
        for (int na = 0; na < 8; na++)
            #pragma unroll
            for (int q = 0; q < 4; q++) acc[ma][na][q] = 0.f;

    const int row = tid >> 1;
    const int ch  = (tid & 1) * 32;

    for (int c = 0; c < 4; c++) {
        const int kc = c * 64;
        #pragma unroll
        for (int q = 0; q < 8; q++) {
            int col = ch + q * 4;
            float4 v = *reinterpret_cast<const float4*>(g_L + (size_t)(rb + row) * DD + kc + col);
            __nv_bfloat16 h0 = __float2bfloat16(v.x), h1 = __float2bfloat16(v.y);
            __nv_bfloat16 h2 = __float2bfloat16(v.z), h3 = __float2bfloat16(v.w);
            __nv_bfloat16 l0 = __float2bfloat16(v.x - __bfloat162float(h0));
            __nv_bfloat16 l1 = __float2bfloat16(v.y - __bfloat162float(h1));
            __nv_bfloat16 l2 = __float2bfloat16(v.z - __bfloat162float(h2));
            __nv_bfloat16 l3 = __float2bfloat16(v.w - __bfloat162float(h3));
            uint32_t boff = row * 128 + col * 2;
            uint32_t sw = boff ^ ((boff >> 3) & 0x70);
            __nv_bfloat162 th0 = __halves2bfloat162(h0, h1), th1 = __halves2bfloat162(h2, h3);
            __nv_bfloat162 tl0 = __halves2bfloat162(l0, l1), tl1 = __halves2bfloat162(l2, l3);
            uint2 uh, ul;
            uh.x = *reinterpret_cast<uint32_t*>(&th0); uh.y = *reinterpret_cast<uint32_t*>(&th1);
            ul.x = *reinterpret_cast<uint32_t*>(&tl0); ul.y = *reinterpret_cast<uint32_t*>(&tl1);
            *reinterpret_cast<uint2*>(smAhi + sw) = uh;
            *reinterpret_cast<uint2*>(smAlo + sw) = ul;
        }
        #pragma unroll
        for (int q = 0; q < 4; q++) {
            int col = ch + q * 8;
            uint32_t boff = row * 128 + col * 2;
            uint32_t sw = boff ^ ((boff >> 3) & 0x70);
            *reinterpret_cast<uint4*>(smBhi + sw) =
                *reinterpret_cast<const uint4*>(g_QWThi + (size_t)(cb + row) * DD + kc + col);
            *reinterpret_cast<uint4*>(smBlo + sw) =
                *reinterpret_cast<const uint4*>(g_QWTlo + (size_t)(cb + row) * DD + kc + col);
        }
        __syncthreads();
        #pragma unroll
        for (int ks = 0; ks < 4; ks++) {
            uint32_t ah[2][4], al[2][4];
            {
                int r = (lane & 7) + ((lane >> 3) & 1) * 8;
                int kb = ks * 32 + ((lane >> 4) & 1) * 16;
                #pragma unroll
                for (int ma = 0; ma < 2; ma++) {
                    uint32_t off = (wm + ma * 16 + r) * 128 + kb;
                    off ^= (off >> 3) & 0x70;
                    LDSM_X4(ah[ma], b32 + off);
                    LDSM_X4(al[ma], b32 + 16384 + off);
                }
            }
            {
                int nr = (lane & 7) + ((lane >> 4) & 1) * 8;
                int kb = ks * 32 + ((lane >> 3) & 1) * 16;
                #pragma unroll
                for (int pr = 0; pr < 4; pr++) {
                    uint32_t off = (wn + pr * 16 + nr) * 128 + kb;
                    off ^= (off >> 3) & 0x70;
                    uint32_t bh[4], bl[4];
                    LDSM_X4(bh, b32 + 32768 + off);
                    LDSM_X4(bl, b32 + 49152 + off);
                    #pragma unroll
                    for (int ma = 0; ma < 2; ma++) {
                        MMA16816(acc[ma][pr * 2 + 0], ah[ma], bh[0], bh[1]);
                        MMA16816(acc[ma][pr * 2 + 0], ah[ma], bl[0], bl[1]);
                        MMA16816(acc[ma][pr * 2 + 0], al[ma], bh[0], bh[1]);
                        MMA16816(acc[ma][pr * 2 + 1], ah[ma], bh[2], bh[3]);
                        MMA16816(acc[ma][pr * 2 + 1], ah[ma], bl[2], bl[3]);
                        MMA16816(acc[ma][pr * 2 + 1], al[ma], bh[2], bh[3]);
                    }
                }
            }
        }
        __syncthreads();
    }

    const int qr = lane >> 2, qc = (lane & 3) * 2;
    float2 bvv[8];
    #pragma unroll
    for (int na = 0; na < 8; na++)
        bvv[na] = *reinterpret_cast<const float2*>(bmix + cb + wn + na * 8 + qc);
    #pragma unroll
    for (int ma = 0; ma < 2; ma++) {
        int R0 = rb + wm + ma * 16 + qr;
        int t0 = R0 >> 4, bb0 = R0 & 15;
        int R1 = R0 + 8;
        int t1 = R1 >> 4, bb1 = R1 & 15;
        float* o0 = out + ((size_t)bb0 * TT + t0) * DD + cb + wn + qc;
        float* o1 = out + ((size_t)bb1 * TT + t1) * DD + cb + wn + qc;
        #pragma unroll
        for (int na = 0; na < 8; na++) {
            *reinterpret_cast<float2*>(o0 + na * 8) =
                make_float2(tanha(acc[ma][na][0] + bvv[na].x),
                            tanha(acc[ma][na][1] + bvv[na].y));
            *reinterpret_cast<float2*>(o1 + na * 8) =
                make_float2(tanha(acc[ma][na][2] + bvv[na].x),
                            tanha(acc[ma][na][3] + bvv[na].y));
        }
    }
}

extern "C" void kernel_launch(void* const* d_in, const int* in_sizes, int n_in,
                              void* d_out, int out_size) {
    const float* x    = (const float*)d_in[0];
    const float* A    = (const float*)d_in[1];
    const float* Bm   = (const float*)d_in[2];
    const float* Wmix = (const float*)d_in[3];
    const float* bmix = (const float*)d_in[4];
    float* out = (float*)d_out;

    cudaFuncSetAttribute(k_y_mma, cudaFuncAttributeMaxDynamicSharedMemorySize, 66560);
    cudaFuncSetAttribute(k_tails2, cudaFuncAttributeMaxDynamicSharedMemorySize, CHSMEM);
    cudaFuncSetAttribute(k_scan2, cudaFuncAttributeMaxDynamicSharedMemorySize, CHSMEM);

    k_prep<<<257, 256>>>(A, Wmix);
    for (int p = 0; p < 5; p++)          // slots 1..5 (M^2 .. M^32)
        k_sq2<<<64, 256>>>(p);
    k_xb<<<dim3(4, 1024), 256>>>(x, Bm);
    k_tails2<<<NJ, 256, CHSMEM>>>();
    for (int lv = 0; lv < 6; lv++)       // combine + fused squaring for next level
        k_hillis<<<NJ + 64, 256>>>(lv);
    k_hillis<<<NJ, 256>>>(6);
    k_scan2<<<NJ, 256, CHSMEM>>>();
    k_y_mma<<<dim3(2, 512), 256, 66560>>>(bmix, out);
}

// round 10
// speedup vs baseline: 3.4012x; 1.0298x over previous
#include <cuda_runtime.h>
#include <cuda_bf16.h>
#include <cstdint>
#include <math.h>

#define TT   4096
#define BB   16
#define DIN  128
#define DD   256
#define MS   (DD*DD)
#define CH   32
#define NJ   128
#define ALPHA (1.0f - 1.0f/128.0f)
#define BETA  (1.0f/128.0f)

// slots p=0..11 hold M^(2^p) (fp32)
__device__ __align__(256) float g_MAT[12 * MS];
__device__ __align__(256) float g_L[(size_t)TT * BB * DD];   // u -> states (in place), [t][b][d]
__device__ __align__(256) float g_VA[NJ * BB * DD];          // transposed tails [j][d][b]
__device__ __align__(256) float g_VB[NJ * BB * DD];
__device__ __align__(256) __nv_bfloat16 g_QWThi[MS];         // QW^T split-hi [unit][d]
__device__ __align__(256) __nv_bfloat16 g_QWTlo[MS];
__device__ __align__(256) __nv_bfloat16 g_MThi[MS];          // M^T split-hi  [n][k]
__device__ __align__(256) __nv_bfloat16 g_MTlo[MS];
__device__ __align__(256) __nv_bfloat16 g_BThi[DD * DIN];    // B^T split-hi  [d][din]
__device__ __align__(256) __nv_bfloat16 g_BTlo[DD * DIN];
__device__ __align__(256) __nv_bfloat16 g_PThi[7 * MS];      // (M^(32*2^lv))^T splits
__device__ __align__(256) __nv_bfloat16 g_PTlo[7 * MS];

// ---------- helpers ----------
__device__ __forceinline__ unsigned long long dup2(float x) {
    unsigned long long r; unsigned u = __float_as_uint(x);
    asm("mov.b64 %0, {%1, %1};" : "=l"(r) : "r"(u));
    return r;
}
__device__ __forceinline__ unsigned long long ffma2(unsigned long long a,
                                                    unsigned long long b,
                                                    unsigned long long c) {
    unsigned long long d;
    asm("fma.rn.f32x2 %0, %1, %2, %3;" : "=l"(d) : "l"(a), "l"(b), "l"(c));
    return d;
}
__device__ __forceinline__ float2 f2(unsigned long long v) {
    unsigned lo, hi;
    asm("mov.b64 {%0, %1}, %2;" : "=r"(lo), "=r"(hi) : "l"(v));
    return make_float2(__uint_as_float(lo), __uint_as_float(hi));
}
__device__ __forceinline__ float tanha(float x) {
    float y; asm("tanh.approx.f32 %0, %1;" : "=f"(y) : "f"(x)); return y;
}
__device__ __forceinline__ uint32_t smem_u32(const void* p) {
    uint32_t a;
    asm("{ .reg .u64 t; cvta.to.shared.u64 t, %1; cvt.u32.u64 %0, t; }" : "=r"(a) : "l"(p));
    return a;
}
#define LDSM_X4(r, a) \
    asm volatile("ldmatrix.sync.aligned.m8n8.x4.shared.b16 {%0,%1,%2,%3}, [%4];" \
        : "=r"((r)[0]), "=r"((r)[1]), "=r"((r)[2]), "=r"((r)[3]) : "r"(a))
#define MMA16816(d, a, b0, b1) \
    asm volatile("mma.sync.aligned.m16n8k16.row.col.f32.bf16.bf16.f32 " \
        "{%0,%1,%2,%3}, {%4,%5,%6,%7}, {%8,%9}, {%0,%1,%2,%3};" \
        : "+f"((d)[0]), "+f"((d)[1]), "+f"((d)[2]), "+f"((d)[3]) \
        : "r"((a)[0]), "r"((a)[1]), "r"((a)[2]), "r"((a)[3]), "r"(b0), "r"(b1))

// ---------- prep ----------
__global__ void __launch_bounds__(256) k_prep(const float* __restrict__ A,
                                              const float* __restrict__ W) {
    int tid = threadIdx.x;
    if (blockIdx.x == 0) {
        float se = 0.f, so = 0.f;
        for (int n = 0; n < 256; n++) {
            float c = (float)(2 * n + 1) * 0.0625f;
            float qw = c * ((n & 1) ? se : so);
            __nv_bfloat16 h = __float2bfloat16(qw);
            g_QWThi[tid * 256 + n] = h;
            g_QWTlo[tid * 256 + n] = __float2bfloat16(qw - __bfloat162float(h));
            float w = W[n * 256 + tid];
            if (n & 1) so += w; else se += w;
        }
    } else {
        int i = (blockIdx.x - 1) * 256 + tid;
        int row = i >> 8, col = i & 255;
        float v = BETA * A[i];
        if (row == col) v += ALPHA;
        g_MAT[i] = v;
        __nv_bfloat16 h = __float2bfloat16(v);
        g_MThi[col * 256 + row] = h;
        g_MTlo[col * 256 + row] = __float2bfloat16(v - __bfloat162float(h));
    }
}

// Bm^T bf16 splits: g_BT*[d][din]
__global__ void __launch_bounds__(256) k_prepb(const float* __restrict__ Bm) {
    int i = blockIdx.x * 256 + threadIdx.x;     // i over 128*256
    int r = i >> 8, c = i & 255;                // Bm[r][c], r<128
    float v = Bm[i];
    __nv_bfloat16 h = __float2bfloat16(v);
    g_BThi[c * DIN + r] = h;
    g_BTlo[c * DIN + r] = __float2bfloat16(v - __bfloat162float(h));
}

// ---------- squaring (32x32 tiles, 64 CTAs); optional transposed bf16 split ----------
__device__ void sq_body(int p, int bid, float* Ast, float* Bs, int pt) {
    const float* __restrict__ X = g_MAT + (size_t)p * MS;
    float* Z = g_MAT + (size_t)(p + 1) * MS;
    const int tid = threadIdx.x;
    const int rb = (bid >> 3) * 32, cb = (bid & 7) * 32;
    const int ty = tid >> 4, tx = tid & 15;
    unsigned long long acc0 = 0ull, acc1 = 0ull;
    const int arow = tid >> 3, ak = (tid & 7) * 4;
    const int bk = tid >> 1, bc = (tid & 1) * 16;
    for (int kc = 0; kc < 256; kc += 128) {
        #pragma unroll
        for (int ii = 0; ii < 4; ii++) {
            int k = ak + ii * 32;
            float4 av = *reinterpret_cast<const float4*>(X + (size_t)(rb + arow) * DD + kc + k);
            Ast[(k + 0) * 34 + arow] = av.x; Ast[(k + 1) * 34 + arow] = av.y;
            Ast[(k + 2) * 34 + arow] = av.z; Ast[(k + 3) * 34 + arow] = av.w;
            *reinterpret_cast<float4*>(&Bs[bk * 32 + bc + ii * 4]) =
                *reinterpret_cast<const float4*>(X + (size_t)(kc + bk) * DD + cb + bc + ii * 4);
        }
        __syncthreads();
        #pragma unroll 8
        for (int k = 0; k < 128; k++) {
            float2 a2 = *reinterpret_cast<const float2*>(&Ast[k * 34 + ty * 2]);
            unsigned long long bv = *reinterpret_cast<const unsigned long long*>(&Bs[k * 32 + tx * 2]);
            acc0 = ffma2(dup2(a2.x), bv, acc0);
            acc1 = ffma2(dup2(a2.y), bv, acc1);
        }
        __syncthreads();
    }
    float2 v0 = f2(acc0), v1 = f2(acc1);
    *reinterpret_cast<float2*>(Z + (size_t)(rb + ty * 2 + 0) * DD + cb + tx * 2) = v0;
    *reinterpret_cast<float2*>(Z + (size_t)(rb + ty * 2 + 1) * DD + cb + tx * 2) = v1;
    if (pt >= 0) {
        __nv_bfloat16* PH = g_PThi + (size_t)pt * MS;
        __nv_bfloat16* PL = g_PTlo + (size_t)pt * MS;
        float vv[2][2] = {{v0.x, v0.y}, {v1.x, v1.y}};
        #pragma unroll
        for (int i = 0; i < 2; i++)
            #pragma unroll
            for (int jj = 0; jj < 2; jj++) {
                float v = vv[i][jj];
                __nv_bfloat16 h = __float2bfloat16(v);
                size_t idx = (size_t)(cb + tx * 2 + jj) * 256 + rb + ty * 2 + i;
                PH[idx] = h;
                PL[idx] = __float2bfloat16(v - __bfloat162float(h));
            }
    }
}

__global__ void __launch_bounds__(256) k_sq2(int p, int pt) {
    __shared__ __align__(16) float sb[8448];
    sq_body(p, blockIdx.x, sb, sb + 4352, pt);
}

// ---------- HMMA u = beta*(x@B): grid (2,512), 128x128 tiles, K=128 ----------
__global__ void __launch_bounds__(256) k_xb_mma(const float* __restrict__ x) {
    extern __shared__ __align__(16) char dsm[];
    const int tid = threadIdx.x;
    const int wid = tid >> 5, lane = tid & 31;
    const int rb = blockIdx.y * 128, cb = blockIdx.x * 128;
    uint32_t raw = smem_u32(dsm);
    uint32_t pad = (1024 - (raw & 1023)) & 1023;
    char* base = dsm + pad;
    uint32_t b32 = raw + pad;
    const int wm = (wid >> 1) * 32, wn = (wid & 1) * 64;
    float acc[2][8][4];
    #pragma unroll
    for (int ma = 0; ma < 2; ma++)
        #pragma unroll
        for (int na = 0; na < 8; na++)
            #pragma unroll
            for (int q = 0; q < 4; q++) acc[ma][na][q] = 0.f;
    const int row = tid >> 1, ch = (tid & 1) * 32;
    for (int c = 0; c < 2; c++) {
        const int kc = c * 64;
        #pragma unroll
        for (int q = 0; q < 8; q++) {
            int col = ch + q * 4;
            float4 v = *reinterpret_cast<const float4*>(x + (size_t)(rb + row) * DIN + kc + col);
            __nv_bfloat16 h0 = __float2bfloat16(v.x), h1 = __float2bfloat16(v.y);
            __nv_bfloat16 h2 = __float2bfloat16(v.z), h3 = __float2bfloat16(v.w);
            __nv_bfloat16 l0 = __float2bfloat16(v.x - __bfloat162float(h0));
            __nv_bfloat16 l1 = __float2bfloat16(v.y - __bfloat162float(h1));
            __nv_bfloat16 l2 = __float2bfloat16(v.z - __bfloat162float(h2));
            __nv_bfloat16 l3 = __float2bfloat16(v.w - __bfloat162float(h3));
            uint32_t boff = row * 128 + col * 2;
            uint32_t sw = boff ^ ((boff >> 3) & 0x70);
            __nv_bfloat162 th0 = __halves2bfloat162(h0, h1), th1 = __halves2bfloat162(h2, h3);
            __nv_bfloat162 tl0 = __halves2bfloat162(l0, l1), tl1 = __halves2bfloat162(l2, l3);
            uint2 uh, ul;
            uh.x = *reinterpret_cast<uint32_t*>(&th0); uh.y = *reinterpret_cast<uint32_t*>(&th1);
            ul.x = *reinterpret_cast<uint32_t*>(&tl0); ul.y = *reinterpret_cast<uint32_t*>(&tl1);
            *reinterpret_cast<uint2*>(base + sw) = uh;
            *reinterpret_cast<uint2*>(base + 16384 + sw) = ul;
        }
        #pragma unroll
        for (int q = 0; q < 4; q++) {
            int col = ch + q * 8;
            uint32_t boff = row * 128 + col * 2;
            uint32_t sw = boff ^ ((boff >> 3) & 0x70);
            *reinterpret_cast<uint4*>(base + 32768 + sw) =
                *reinterpret_cast<const uint4*>(g_BThi + (size_t)(cb + row) * DIN + kc + col);
            *reinterpret_cast<uint4*>(base + 49152 + sw) =
                *reinterpret_cast<const uint4*>(g_BTlo + (size_t)(cb + row) * DIN + kc + col);
        }
        __syncthreads();
        #pragma unroll
        for (int ks = 0; ks < 4; ks++) {
            uint32_t ah[2][4], al[2][4];
            {
                int r = (lane & 7) + ((lane >> 3) & 1) * 8;
                int kb = ks * 32 + ((lane >> 4) & 1) * 16;
                #pragma unroll
                for (int ma = 0; ma < 2; ma++) {
                    uint32_t off = (wm + ma * 16 + r) * 128 + kb;
                    off ^= (off >> 3) & 0x70;
                    LDSM_X4(ah[ma], b32 + off);
                    LDSM_X4(al[ma], b32 + 16384 + off);
                }
            }
            {
                int nr = (lane & 7) + ((lane >> 4) & 1) * 8;
                int kb = ks * 32 + ((lane >> 3) & 1) * 16;
                #pragma unroll
                for (int pr = 0; pr < 4; pr++) {
                    uint32_t off = (wn + pr * 16 + nr) * 128 + kb;
                    off ^= (off >> 3) & 0x70;
                    uint32_t bh[4], bl[4];
                    LDSM_X4(bh, b32 + 32768 + off);
                    LDSM_X4(bl, b32 + 49152 + off);
                    #pragma unroll
                    for (int ma = 0; ma < 2; ma++) {
                        MMA16816(acc[ma][pr * 2 + 0], ah[ma], bh[0], bh[1]);
                        MMA16816(acc[ma][pr * 2 + 0], ah[ma], bl[0], bl[1]);
                        MMA16816(acc[ma][pr * 2 + 0], al[ma], bh[0], bh[1]);
                        MMA16816(acc[ma][pr * 2 + 1], ah[ma], bh[2], bh[3]);
                        MMA16816(acc[ma][pr * 2 + 1], ah[ma], bl[2], bl[3]);
                        MMA16816(acc[ma][pr * 2 + 1], al[ma], bh[2], bh[3]);
                    }
                }
            }
        }
        __syncthreads();
    }
    const int qr = lane >> 2, qc = (lane & 3) * 2;
    #pragma unroll
    for (int ma = 0; ma < 2; ma++) {
        int R0 = rb + wm + ma * 16 + qr;
        int b0i = R0 >> 12, t0 = R0 & 4095;
        int R1 = R0 + 8;
        int b1i = R1 >> 12, t1 = R1 & 4095;
        float* o0 = g_L + ((size_t)t0 * BB + b0i) * DD + cb + wn + qc;
        float* o1 = g_L + ((size_t)t1 * BB + b1i) * DD + cb + wn + qc;
        #pragma unroll
        for (int na = 0; na < 8; na++) {
            *reinterpret_cast<float2*>(o0 + na * 8) =
                make_float2(BETA * acc[ma][na][0], BETA * acc[ma][na][1]);
            *reinterpret_cast<float2*>(o1 + na * 8) =
                make_float2(BETA * acc[ma][na][2], BETA * acc[ma][na][3]);
        }
    }
}

// ---------- HMMA chunk recurrence ----------
#define MTLO_OFF 0
#define SH_OFF   135168
#define SL_OFF   152064
#define CHSMEM   168960
template<bool WRITE_STATE, bool FROM_INIT>
__device__ void chunk_mma(int j) {
    extern __shared__ __align__(16) char cs[];
    __nv_bfloat16* MTlo = reinterpret_cast<__nv_bfloat16*>(cs + MTLO_OFF);   // [256][264]
    const int tid = threadIdx.x, lane = tid & 31, wid = tid >> 5;
    const int wn = wid * 32;
    const int qr = lane >> 2, qc = (lane & 3) * 2;
    {
        const uint4* s = reinterpret_cast<const uint4*>(g_MTlo + (size_t)tid * 256);
        uint4* d = reinterpret_cast<uint4*>(MTlo + (size_t)tid * 264);
        #pragma unroll
        for (int i = 0; i < 32; i++) d[i] = s[i];
    }
    uint32_t Bhi[16][4][2];
    {
        const int bn = lane >> 2, bk = (lane & 3) * 2;
        #pragma unroll
        for (int q = 0; q < 16; q++)
            #pragma unroll
            for (int na = 0; na < 4; na++) {
                const __nv_bfloat16* p = g_MThi + (size_t)(wn + na * 8 + bn) * 256 + q * 16 + bk;
                Bhi[q][na][0] = *reinterpret_cast<const uint32_t*>(p);
                Bhi[q][na][1] = *reinterpret_cast<const uint32_t*>(p + 8);
            }
    }
    if (FROM_INIT && j) {
        const float* ip = g_VB + (size_t)(j - 1) * 4096;
        for (int f = tid; f < 4096; f += 256) {
            int d = f >> 4, b = f & 15;
            float v = ip[f];
            __nv_bfloat16 h = __float2bfloat16(v);
            *reinterpret_cast<__nv_bfloat16*>(cs + SH_OFF + b * 528 + d * 2) = h;
            *reinterpret_cast<__nv_bfloat16*>(cs + SL_OFF + b * 528 + d * 2) =
                __float2bfloat16(v - __bfloat162float(h));
        }
    } else {
        for (int f = tid; f < 4096; f += 256) {
            int d = f >> 4, b = f & 15;
            *reinterpret_cast<unsigned short*>(cs + SH_OFF + b * 528 + d * 2) = 0;
            *reinterpret_cast<unsigned short*>(cs + SL_OFF + b * 528 + d * 2) = 0;
        }
    }
    __syncthreads();
    const uint32_t base32 = smem_u32(cs);
    const int arow = (lane & 7) + ((lane >> 3) & 1) * 8;
    const uint32_t aoff = arow * 528 + ((lane >> 4) & 1) * 16;
    const int nr = (lane & 7) + ((lane >> 4) & 1) * 8;
    const uint32_t boff0 = base32 + MTLO_OFF + (wn +  0 + nr) * 528 + ((lane >> 3) & 1) * 16;
    const uint32_t boff1 = base32 + MTLO_OFF + (wn + 16 + nr) * 528 + ((lane >> 3) & 1) * 16;
    float2 u0[4], u1[4];
    {
        const float* up = g_L + (size_t)(j * CH) * 4096;
        #pragma unroll
        for (int na = 0; na < 4; na++) {
            int col = wn + na * 8 + qc;
            u0[na] = *reinterpret_cast<const float2*>(up + (size_t)qr * 256 + col);
            u1[na] = *reinterpret_cast<const float2*>(up + (size_t)(qr + 8) * 256 + col);
        }
    }
    int cur = 0;
    for (int r = 0; r < CH; r++) {
        const int t = j * CH + r;
        float acc[4][4];
        #pragma unroll
        for (int na = 0; na < 4; na++) {
            acc[na][0] = u0[na].x; acc[na][1] = u0[na].y;
            acc[na][2] = u1[na].x; acc[na][3] = u1[na].y;
        }
        if (r + 1 < CH) {
            const float* up = g_L + (size_t)(t + 1) * 4096;
            #pragma unroll
            for (int na = 0; na < 4; na++) {
                int col = wn + na * 8 + qc;
                u0[na] = *reinterpret_cast<const float2*>(up + (size_t)qr * 256 + col);
                u1[na] = *reinterpret_cast<const float2*>(up + (size_t)(qr + 8) * 256 + col);
            }
        }
        const uint32_t shb = base32 + (cur ? SH_OFF + 8448 : SH_OFF) + aoff;
        const uint32_t slb = base32 + (cur ? SL_OFF + 8448 : SL_OFF) + aoff;
        #pragma unroll
        for (int q = 0; q < 16; q++) {
            uint32_t ah[4], al[4], bl0[4], bl1[4];
            LDSM_X4(ah, shb + q * 32);
            LDSM_X4(al, slb + q * 32);
            LDSM_X4(bl0, boff0 + q * 32);
            LDSM_X4(bl1, boff1 + q * 32);
            MMA16816(acc[0], ah, Bhi[q][0][0], Bhi[q][0][1]);
            MMA16816(acc[0], al, Bhi[q][0][0], Bhi[q][0][1]);
            MMA16816(acc[0], ah, bl0[0], bl0[1]);
            MMA16816(acc[1], ah, Bhi[q][1][0], Bhi[q][1][1]);
            MMA16816(acc[1], al, Bhi[q][1][0], Bhi[q][1][1]);
            MMA16816(acc[1], ah, bl0[2], bl0[3]);
            MMA16816(acc[2], ah, Bhi[q][2][0], Bhi[q][2][1]);
            MMA16816(acc[2], al, Bhi[q][2][0], Bhi[q][2][1]);
            MMA16816(acc[2], ah, bl1[0], bl1[1]);
            MMA16816(acc[3], ah, Bhi[q][3][0], Bhi[q][3][1]);
            MMA16816(acc[3], al, Bhi[q][3][0], Bhi[q][3][1]);
            MMA16816(acc[3], ah, bl1[2], bl1[3]);
        }
        if (!WRITE_STATE && r == CH - 1) {
            float* tp = g_VA + (size_t)j * 4096;
            #pragma unroll
            for (int na = 0; na < 4; na++) {
                int col = wn + na * 8 + qc;
                tp[(col + 0) * 16 + qr]     = acc[na][0];
                tp[(col + 1) * 16 + qr]     = acc[na][1];
                tp[(col + 0) * 16 + qr + 8] = acc[na][2];
                tp[(col + 1) * 16 + qr + 8] = acc[na][3];
            }
        } else {
            const int nxt = cur ^ 1;
            char* shn = cs + (nxt ? SH_OFF + 8448 : SH_OFF);
            char* sln = cs + (nxt ? SL_OFF + 8448 : SL_OFF);
            #pragma unroll
            for (int na = 0; na < 4; na++) {
                int col = wn + na * 8 + qc;
                {
                    float v0 = acc[na][0], v1 = acc[na][1];
                    __nv_bfloat16 h0 = __float2bfloat16(v0), h1 = __float2bfloat16(v1);
                    __nv_bfloat162 hh = __halves2bfloat162(h0, h1);
                    __nv_bfloat162 ll = __halves2bfloat162(
                        __float2bfloat16(v0 - __bfloat162float(h0)),
                        __float2bfloat16(v1 - __bfloat162float(h1)));
                    *reinterpret_cast<uint32_t*>(shn + qr * 528 + col * 2) =
                        *reinterpret_cast<uint32_t*>(&hh);
                    *reinterpret_cast<uint32_t*>(sln + qr * 528 + col * 2) =
                        *reinterpret_cast<uint32_t*>(&ll);
                }
                {
                    float v0 = acc[na][2], v1 = acc[na][3];
                    __nv_bfloat16 h0 = __float2bfloat16(v0), h1 = __float2bfloat16(v1);
                    __nv_bfloat162 hh = __halves2bfloat162(h0, h1);
                    __nv_bfloat162 ll = __halves2bfloat162(
                        __float2bfloat16(v0 - __bfloat162float(h0)),
                        __float2bfloat16(v1 - __bfloat162float(h1)));
                    *reinterpret_cast<uint32_t*>(shn + (qr + 8) * 528 + col * 2) =
                        *reinterpret_cast<uint32_t*>(&hh);
                    *reinterpret_cast<uint32_t*>(sln + (qr + 8) * 528 + col * 2) =
                        *reinterpret_cast<uint32_t*>(&ll);
                }
                if (WRITE_STATE) {
                    float* sp = g_L + (size_t)t * 4096;
                    *reinterpret_cast<float2*>(sp + (size_t)qr * 256 + col) =
                        make_float2(acc[na][0], acc[na][1]);
                    *reinterpret_cast<float2*>(sp + (size_t)(qr + 8) * 256 + col) =
                        make_float2(acc[na][2], acc[na][3]);
                }
            }
            __syncthreads();
            cur = nxt;
        }
    }
}

__global__ void __launch_bounds__(256) k_tails2() { chunk_mma<false, false>(blockIdx.x); }
__global__ void __launch_bounds__(256) k_scan2()  { chunk_mma<true,  true >(blockIdx.x); }

// ---------- HMMA Hillis combine + fused next-power squaring ----------
__global__ void __launch_bounds__(256) k_hillis2(int level) {
    __shared__ __align__(16) char hbuf[33792];
    int cta = blockIdx.x;
    if (cta >= NJ) {
        if (level < 6)
            sq_body(5 + level, cta - NJ, (float*)hbuf, (float*)hbuf + 4352, level + 1);
        return;
    }
    const float* in  = (level & 1) ? g_VB : g_VA;
    float*       out = (level & 1) ? g_VA : g_VB;
    const int tid = threadIdx.x;
    int j = cta, sft = 1 << level;
    const float* inj = in + (size_t)j * 4096;
    float*      outj = out + (size_t)j * 4096;
    if (j < sft) {
        for (int f = tid * 4; f < 4096; f += 1024)
            *reinterpret_cast<float4*>(outj + f) = *reinterpret_cast<const float4*>(inj + f);
        return;
    }
    // stage prev tail as A hi/lo (16 rows x 256 k, 528B stride)
    const float* ip = in + (size_t)(j - sft) * 4096;
    for (int f = tid; f < 4096; f += 256) {
        int d = f >> 4, b = f & 15;
        float v = ip[f];
        __nv_bfloat16 h = __float2bfloat16(v);
        *reinterpret_cast<__nv_bfloat16*>(hbuf + b * 528 + d * 2) = h;
        *reinterpret_cast<__nv_bfloat16*>(hbuf + 8448 + b * 528 + d * 2) =
            __float2bfloat16(v - __bfloat162float(h));
    }
    __syncthreads();
    const int lane = tid & 31, wid = tid >> 5;
    const int wn = wid * 32;
    const int qr = lane >> 2, qc = (lane & 3) * 2;
    float acc[4][4];
    #pragma unroll
    for (int na = 0; na < 4; na++) {
        int col = wn + na * 8 + qc;
        acc[na][0] = inj[(col + 0) * 16 + qr];
        acc[na][1] = inj[(col + 1) * 16 + qr];
        acc[na][2] = inj[(col + 0) * 16 + qr + 8];
        acc[na][3] = inj[(col + 1) * 16 + qr + 8];
    }
    const uint32_t base32 = smem_u32(hbuf);
    const int arow = (lane & 7) + ((lane >> 3) & 1) * 8;
    const uint32_t aoff = arow * 528 + ((lane >> 4) & 1) * 16;
    const __nv_bfloat16* PH = g_PThi + (size_t)level * MS;
    const __nv_bfloat16* PL = g_PTlo + (size_t)level * MS;
    const int bn = lane >> 2, bk = (lane & 3) * 2;
    #pragma unroll
    for (int q = 0; q < 16; q++) {
        uint32_t ah[4], al[4];
        LDSM_X4(ah, base32 + aoff + q * 32);
        LDSM_X4(al, base32 + 8448 + aoff + q * 32);
        #pragma unroll
        for (int na = 0; na < 4; na++) {
            const __nv_bfloat16* ph = PH + (size_t)(wn + na * 8 + bn) * 256 + q * 16 + bk;
            const __nv_bfloat16* pl = PL + (size_t)(wn + na * 8 + bn) * 256 + q * 16 + bk;
            uint32_t bh0 = *reinterpret_cast<const uint32_t*>(ph);
            uint32_t bh1 = *reinterpret_cast<const uint32_t*>(ph + 8);
            uint32_t bl0 = *reinterpret_cast<const uint32_t*>(pl);
            uint32_t bl1 = *reinterpret_cast<const uint32_t*>(pl + 8);
            MMA16816(acc[na], ah, bh0, bh1);
            MMA16816(acc[na], al, bh0, bh1);
            MMA16816(acc[na], ah, bl0, bl1);
        }
    }
    #pragma unroll
    for (int na = 0; na < 4; na++) {
        int col = wn + na * 8 + qc;
        outj[(col + 0) * 16 + qr]     = acc[na][0];
        outj[(col + 1) * 16 + qr]     = acc[na][1];
        outj[(col + 0) * 16 + qr + 8] = acc[na][2];
        outj[(col + 1) * 16 + qr + 8] = acc[na][3];
    }
}

// ---------- warp-MMA y ----------
__global__ void __launch_bounds__(256) k_y_mma(const float* __restrict__ bmix,
                                               float* __restrict__ out) {
    extern __shared__ __align__(16) char dsm[];
    const int tid = threadIdx.x;
    const int wid = tid >> 5, lane = tid & 31;
    const int rb = blockIdx.y * 128, cb = blockIdx.x * 128;
    uint32_t raw = smem_u32(dsm);
    uint32_t pad = (1024 - (raw & 1023)) & 1023;
    char* base = dsm + pad;
    uint32_t b32 = raw + pad;
    const int wm = (wid >> 1) * 32, wn = (wid & 1) * 64;
    float acc[2][8][4];
    #pragma unroll
    for (int ma = 0; ma < 2; ma++)
        #pragma unroll
        for (int na = 0; na < 8; na++)
            #pragma unroll
            for (int q = 0; q < 4; q++) acc[ma][na][q] = 0.f;
    const int row = tid >> 1, ch = (tid & 1) * 32;
    for (int c = 0; c < 4; c++) {
        const int kc = c * 64;
        #pragma unroll
        for (int q = 0; q < 8; q++) {
            int col = ch + q * 4;
            float4 v = *reinterpret_cast<const float4*>(g_L + (size_t)(rb + row) * DD + kc + col);
            __nv_bfloat16 h0 = __float2bfloat16(v.x), h1 = __float2bfloat16(v.y);
            __nv_bfloat16 h2 = __float2bfloat16(v.z), h3 = __float2bfloat16(v.w);
            __nv_bfloat16 l0 = __float2bfloat16(v.x - __bfloat162float(h0));
            __nv_bfloat16 l1 = __float2bfloat16(v.y - __bfloat162float(h1));
            __nv_bfloat16 l2 = __float2bfloat16(v.z - __bfloat162float(h2));
            __nv_bfloat16 l3 = __float2bfloat16(v.w - __bfloat162float(h3));
            uint32_t boff = row * 128 + col * 2;
            uint32_t sw = boff ^ ((boff >> 3) & 0x70);
            __nv_bfloat162 th0 = __halves2bfloat162(h0, h1), th1 = __halves2bfloat162(h2, h3);
            __nv_bfloat162 tl0 = __halves2bfloat162(l0, l1), tl1 = __halves2bfloat162(l2, l3);
            uint2 uh, ul;
            uh.x = *reinterpret_cast<uint32_t*>(&th0); uh.y = *reinterpret_cast<uint32_t*>(&th1);
            ul.x = *reinterpret_cast<uint32_t*>(&tl0); ul.y = *reinterpret_cast<uint32_t*>(&tl1);
            *reinterpret_cast<uint2*>(base + sw) = uh;
            *reinterpret_cast<uint2*>(base + 16384 + sw) = ul;
        }
        #pragma unroll
        for (int q = 0; q < 4; q++) {
            int col = ch + q * 8;
            uint32_t boff = row * 128 + col * 2;
            uint32_t sw = boff ^ ((boff >> 3) & 0x70);
            *reinterpret_cast<uint4*>(base + 32768 + sw) =
                *reinterpret_cast<const uint4*>(g_QWThi + (size_t)(cb + row) * DD + kc + col);
            *reinterpret_cast<uint4*>(base + 49152 + sw) =
                *reinterpret_cast<const uint4*>(g_QWTlo + (size_t)(cb + row) * DD + kc + col);
        }
        __syncthreads();
        #pragma unroll
        for (int ks = 0; ks < 4; ks++) {
            uint32_t ah[2][4], al[2][4];
            {
                int r = (lane & 7) + ((lane >> 3) & 1) * 8;
                int kb = ks * 32 + ((lane >> 4) & 1) * 16;
                #pragma unroll
                for (int ma = 0; ma < 2; ma++) {
                    uint32_t off = (wm + ma * 16 + r) * 128 + kb;
                    off ^= (off >> 3) & 0x70;
                    LDSM_X4(ah[ma], b32 + off);
                    LDSM_X4(al[ma], b32 + 16384 + off);
                }
            }
            {
                int nr = (lane & 7) + ((lane >> 4) & 1) * 8;
                int kb = ks * 32 + ((lane >> 3) & 1) * 16;
                #pragma unroll
                for (int pr = 0; pr < 4; pr++) {
                    uint32_t off = (wn + pr * 16 + nr) * 128 + kb;
                    off ^= (off >> 3) & 0x70;
                    uint32_t bh[4], bl[4];
                    LDSM_X4(bh, b32 + 32768 + off);
                    LDSM_X4(bl, b32 + 49152 + off);
                    #pragma unroll
                    for (int ma = 0; ma < 2; ma++) {
                        MMA16816(acc[ma][pr * 2 + 0], ah[ma], bh[0], bh[1]);
                        MMA16816(acc[ma][pr * 2 + 0], ah[ma], bl[0], bl[1]);
                        MMA16816(acc[ma][pr * 2 + 0], al[ma], bh[0], bh[1]);
                        MMA16816(acc[ma][pr * 2 + 1], ah[ma], bh[2], bh[3]);
                        MMA16816(acc[ma][pr * 2 + 1], ah[ma], bl[2], bl[3]);
                        MMA16816(acc[ma][pr * 2 + 1], al[ma], bh[2], bh[3]);
                    }
                }
            }
        }
        __syncthreads();
    }
    const int qr = lane >> 2, qc = (lane & 3) * 2;
    float2 bvv[8];
    #pragma unroll
    for (int na = 0; na < 8; na++)
        bvv[na] = *reinterpret_cast<const float2*>(bmix + cb + wn + na * 8 + qc);
    #pragma unroll
    for (int ma = 0; ma < 2; ma++) {
        int R0 = rb + wm + ma * 16 + qr;
        int t0 = R0 >> 4, bb0 = R0 & 15;
        int R1 = R0 + 8;
        int t1 = R1 >> 4, bb1 = R1 & 15;
        float* o0 = out + ((size_t)bb0 * TT + t0) * DD + cb + wn + qc;
        float* o1 = out + ((size_t)bb1 * TT + t1) * DD + cb + wn + qc;
        #pragma unroll
        for (int na = 0; na < 8; na++) {
            *reinterpret_cast<float2*>(o0 + na * 8) =
                make_float2(tanha(acc[ma][na][0] + bvv[na].x),
                            tanha(acc[ma][na][1] + bvv[na].y));
            *reinterpret_cast<float2*>(o1 + na * 8) =
                make_float2(tanha(acc[ma][na][2] + bvv[na].x),
                            tanha(acc[ma][na][3] + bvv[na].y));
        }
    }
}

extern "C" void kernel_launch(void* const* d_in, const int* in_sizes, int n_in,
                              void* d_out, int out_size) {
    const float* x    = (const float*)d_in[0];
    const float* A    = (const float*)d_in[1];
    const float* Bm   = (const float*)d_in[2];
    const float* Wmix = (const float*)d_in[3];
    const float* bmix = (const float*)d_in[4];
    float* out = (float*)d_out;

    cudaFuncSetAttribute(k_y_mma, cudaFuncAttributeMaxDynamicSharedMemorySize, 66560);
    cudaFuncSetAttribute(k_xb_mma, cudaFuncAttributeMaxDynamicSharedMemorySize, 66560);
    cudaFuncSetAttribute(k_tails2, cudaFuncAttributeMaxDynamicSharedMemorySize, CHSMEM);
    cudaFuncSetAttribute(k_scan2, cudaFuncAttributeMaxDynamicSharedMemorySize, CHSMEM);

    k_prep<<<257, 256>>>(A, Wmix);
    k_prepb<<<128, 256>>>(Bm);
    for (int p = 0; p < 5; p++)                 // slots 1..5; p=4 emits PT[0] (M^32 split)
        k_sq2<<<64, 256>>>(p, p == 4 ? 0 : -1);
    k_xb_mma<<<dim3(2, 512), 256, 66560>>>(x);
    k_tails2<<<NJ, 256, CHSMEM>>>();
    for (int lv = 0; lv < 6; lv++)              // combine lv + fused sq -> PT[lv+1]
        k_hillis2<<<NJ + 64, 256>>>(lv);
    k_hillis2<<<NJ, 256>>>(6);
    k_scan2<<<NJ, 256, CHSMEM>>>();
    k_y_mma<<<dim3(2, 512), 256, 66560>>>(bmix, out);
}